// round 1
// baseline (speedup 1.0000x reference)
#include <cuda_runtime.h>
#include <math.h>

#define BB 2
#define TT 4096
#define DD 512
#define HH 8
#define HK 64
#define FF 2048
#define MM (BB*TT)   // 8192 rows

// ---------------- scratch (no allocs allowed) ----------------
__device__ float g_x1 [MM*DD];
__device__ float g_q  [MM*DD];
__device__ float g_k  [MM*DD];
__device__ float g_v  [MM*DD];
__device__ float g_ctx[MM*DD];
__device__ float g_x  [MM*DD];
__device__ float g_y  [MM*DD];
__device__ float g_h  [MM*FF];

// ---------------- LayerNorm: one row (D=512) per block, 128 threads ----------------
__global__ void __launch_bounds__(128) ln_kernel(const float* __restrict__ x,
                                                 const float* __restrict__ sc,
                                                 const float* __restrict__ of,
                                                 float* __restrict__ out) {
    int row = blockIdx.x;
    int tid = threadIdx.x;
    const float4* xr = (const float4*)(x + (size_t)row * DD);
    float4 v = xr[tid];
    float s  = v.x + v.y + v.z + v.w;
    float ss = v.x*v.x + v.y*v.y + v.z*v.z + v.w*v.w;
    #pragma unroll
    for (int o = 16; o > 0; o >>= 1) {
        s  += __shfl_xor_sync(0xffffffffu, s,  o);
        ss += __shfl_xor_sync(0xffffffffu, ss, o);
    }
    __shared__ float s_s[4], s_ss[4];
    int wid = tid >> 5, lane = tid & 31;
    if (lane == 0) { s_s[wid] = s; s_ss[wid] = ss; }
    __syncthreads();
    s  = s_s[0]  + s_s[1]  + s_s[2]  + s_s[3];
    ss = s_ss[0] + s_ss[1] + s_ss[2] + s_ss[3];
    float mean = s * (1.0f / DD);
    float var  = ss * (1.0f / DD) - mean * mean;
    float inv  = rsqrtf(var + 1e-5f);
    float4 scv = ((const float4*)sc)[tid];
    float4 ofv = ((const float4*)of)[tid];
    float4 o;
    o.x = (v.x - mean) * inv * scv.x + ofv.x;
    o.y = (v.y - mean) * inv * scv.y + ofv.y;
    o.z = (v.z - mean) * inv * scv.z + ofv.z;
    o.w = (v.w - mean) * inv * scv.w + ofv.w;
    ((float4*)(out + (size_t)row * DD))[tid] = o;
}

// ---------------- GEMM: C[M,N] = A[M,Kd] @ B[Kd,N] + bias (+epilogue) ----------------
// EPI: 0 = bias only, 1 = bias + tanh-GELU, 2 = bias + residual
__device__ __forceinline__ float gelu_tanh(float x) {
    float x3 = x * x * x;
    return 0.5f * x * (1.0f + tanhf(0.7978845608028654f * (x + 0.044715f * x3)));
}

template <int EPI>
__global__ void __launch_bounds__(256) gemm_kernel(const float* __restrict__ A,
                                                   const float* __restrict__ B,
                                                   const float* __restrict__ bias,
                                                   const float* __restrict__ res,
                                                   float* __restrict__ C,
                                                   int M, int N, int Kd) {
    __shared__ float As[16][64];   // As[k][m]  (A transposed in smem)
    __shared__ float Bs[16][64];   // Bs[k][n]
    int tid = threadIdx.x;
    int tx = tid & 15, ty = tid >> 4;
    int m0 = blockIdx.y * 64;
    int n0 = blockIdx.x * 64;

    float acc[4][4];
    #pragma unroll
    for (int i = 0; i < 4; i++)
        #pragma unroll
        for (int j = 0; j < 4; j++) acc[i][j] = 0.0f;

    int arow = (tid >> 2);             // 0..63 (within tile)
    int acol4 = (tid & 3) * 4;         // 0,4,8,12
    int brow = tid >> 4;               // 0..15
    int bcol4 = (tid & 15) * 4;        // 0..60
    const float* Aptr = A + (size_t)(m0 + arow) * Kd + acol4;
    const float* Bptr = B + (size_t)brow * N + n0 + bcol4;

    for (int k0 = 0; k0 < Kd; k0 += 16) {
        float4 av = *(const float4*)(Aptr + k0);
        float4 bv = *(const float4*)(Bptr + (size_t)k0 * N);
        __syncthreads();
        As[acol4 + 0][arow] = av.x;
        As[acol4 + 1][arow] = av.y;
        As[acol4 + 2][arow] = av.z;
        As[acol4 + 3][arow] = av.w;
        *(float4*)&Bs[brow][bcol4] = bv;
        __syncthreads();
        #pragma unroll
        for (int kk = 0; kk < 16; kk++) {
            float4 a = *(const float4*)&As[kk][ty * 4];
            float4 b = *(const float4*)&Bs[kk][tx * 4];
            acc[0][0] += a.x * b.x; acc[0][1] += a.x * b.y; acc[0][2] += a.x * b.z; acc[0][3] += a.x * b.w;
            acc[1][0] += a.y * b.x; acc[1][1] += a.y * b.y; acc[1][2] += a.y * b.z; acc[1][3] += a.y * b.w;
            acc[2][0] += a.z * b.x; acc[2][1] += a.z * b.y; acc[2][2] += a.z * b.z; acc[2][3] += a.z * b.w;
            acc[3][0] += a.w * b.x; acc[3][1] += a.w * b.y; acc[3][2] += a.w * b.z; acc[3][3] += a.w * b.w;
        }
    }

    int row = m0 + ty * 4;
    int col = n0 + tx * 4;
    float4 bz = *(const float4*)&bias[col];
    #pragma unroll
    for (int i = 0; i < 4; i++) {
        float4 o;
        o.x = acc[i][0] + bz.x;
        o.y = acc[i][1] + bz.y;
        o.z = acc[i][2] + bz.z;
        o.w = acc[i][3] + bz.w;
        if (EPI == 1) {
            o.x = gelu_tanh(o.x); o.y = gelu_tanh(o.y);
            o.z = gelu_tanh(o.z); o.w = gelu_tanh(o.w);
        }
        if (EPI == 2) {
            float4 r = *(const float4*)&res[(size_t)(row + i) * N + col];
            o.x += r.x; o.y += r.y; o.z += r.z; o.w += r.w;
        }
        *(float4*)&C[(size_t)(row + i) * N + col] = o;
    }
}

// ---------------- Flash attention (fp32, online softmax) ----------------
// grid: (T/64, B*H), block 256. Q/K/V laid out [B,T,H*K]; head h at col offset h*64.
// Each block: 64 query rows, streams keys in tiles of 32.
// Thread owns q-row qr=tid/4; computes 8 logit cols (tid%4)*8.. and 16 out dims (tid%4)*16..
__global__ void __launch_bounds__(256) attn_kernel(const float* __restrict__ Q,
                                                   const float* __restrict__ Kg,
                                                   const float* __restrict__ Vg,
                                                   float* __restrict__ Og) {
    __shared__ float Qs [64][64];   // 16 KB
    __shared__ float Kst[64][32];   // 8 KB, transposed: [dim][key]
    __shared__ float Vs [32][64];   // 8 KB
    __shared__ float Ps [64][32];   // 8 KB
    int b = blockIdx.y >> 3;
    int h = blockIdx.y & 7;
    int qt = blockIdx.x * 64;
    int tid = threadIdx.x;

    const float* Qb = Q  + ((size_t)b * TT) * DD + h * HK;
    const float* Kb = Kg + ((size_t)b * TT) * DD + h * HK;
    const float* Vb = Vg + ((size_t)b * TT) * DD + h * HK;

    // load Q tile, pre-scaled by 1/sqrt(K)
    for (int i = tid; i < 64 * 64; i += 256) {
        int r = i >> 6, d = i & 63;
        Qs[r][d] = Qb[(size_t)(qt + r) * DD + d] * 0.125f;
    }

    int qr = tid >> 2;
    int c0 = (tid & 3) * 8;
    int d0 = (tid & 3) * 16;
    float m = -1e30f, l = 0.0f;
    float o[16];
    #pragma unroll
    for (int j = 0; j < 16; j++) o[j] = 0.0f;

    for (int kt = 0; kt < TT; kt += 32) {
        __syncthreads();
        for (int i = tid; i < 32 * 64; i += 256) {
            int key = i >> 6, d = i & 63;
            Kst[d][key] = Kb[(size_t)(kt + key) * DD + d];
            Vs[key][d]  = Vb[(size_t)(kt + key) * DD + d];
        }
        __syncthreads();

        // S = Qs @ Kst  (8 cols per thread)
        float s[8];
        #pragma unroll
        for (int j = 0; j < 8; j++) s[j] = 0.0f;
        #pragma unroll 4
        for (int kk = 0; kk < 64; kk++) {
            float qv = Qs[qr][kk];
            float4 k1 = *(const float4*)&Kst[kk][c0];
            float4 k2 = *(const float4*)&Kst[kk][c0 + 4];
            s[0] += qv * k1.x; s[1] += qv * k1.y; s[2] += qv * k1.z; s[3] += qv * k1.w;
            s[4] += qv * k2.x; s[5] += qv * k2.y; s[6] += qv * k2.z; s[7] += qv * k2.w;
        }

        // online softmax update (4 threads per q-row, adjacent lanes)
        float tmax = s[0];
        #pragma unroll
        for (int j = 1; j < 8; j++) tmax = fmaxf(tmax, s[j]);
        tmax = fmaxf(tmax, __shfl_xor_sync(0xffffffffu, tmax, 1));
        tmax = fmaxf(tmax, __shfl_xor_sync(0xffffffffu, tmax, 2));
        float newm = fmaxf(m, tmax);
        float alpha = __expf(m - newm);
        float tsum = 0.0f;
        #pragma unroll
        for (int j = 0; j < 8; j++) {
            float p = __expf(s[j] - newm);
            Ps[qr][c0 + j] = p;
            tsum += p;
        }
        tsum += __shfl_xor_sync(0xffffffffu, tsum, 1);
        tsum += __shfl_xor_sync(0xffffffffu, tsum, 2);
        l = l * alpha + tsum;
        m = newm;
        #pragma unroll
        for (int j = 0; j < 16; j++) o[j] *= alpha;
        __syncwarp();   // Ps written/read within the same 4-lane group

        // O += P @ V  (16 dims per thread)
        #pragma unroll 4
        for (int sidx = 0; sidx < 32; sidx++) {
            float p = Ps[qr][sidx];
            float4 v1 = *(const float4*)&Vs[sidx][d0];
            float4 v2 = *(const float4*)&Vs[sidx][d0 + 4];
            float4 v3 = *(const float4*)&Vs[sidx][d0 + 8];
            float4 v4 = *(const float4*)&Vs[sidx][d0 + 12];
            o[0]  += p * v1.x; o[1]  += p * v1.y; o[2]  += p * v1.z; o[3]  += p * v1.w;
            o[4]  += p * v2.x; o[5]  += p * v2.y; o[6]  += p * v2.z; o[7]  += p * v2.w;
            o[8]  += p * v3.x; o[9]  += p * v3.y; o[10] += p * v3.z; o[11] += p * v3.w;
            o[12] += p * v4.x; o[13] += p * v4.y; o[14] += p * v4.z; o[15] += p * v4.w;
        }
    }

    float invl = 1.0f / l;
    float* Ob = Og + ((size_t)b * TT + qt + qr) * DD + h * HK + d0;
    #pragma unroll
    for (int j = 0; j < 16; j++) Ob[j] = o[j] * invl;
}

// ---------------- launch ----------------
extern "C" void kernel_launch(void* const* d_in, const int* in_sizes, int n_in,
                              void* d_out, int out_size) {
    const float* inputs     = (const float*)d_in[0];
    const float* ln1_scale  = (const float*)d_in[1];
    const float* ln1_offset = (const float*)d_in[2];
    const float* wq = (const float*)d_in[3];
    const float* bq = (const float*)d_in[4];
    const float* wk = (const float*)d_in[5];
    const float* bk = (const float*)d_in[6];
    const float* wv = (const float*)d_in[7];
    const float* bv = (const float*)d_in[8];
    const float* wo = (const float*)d_in[9];
    const float* bo = (const float*)d_in[10];
    const float* ln2_scale  = (const float*)d_in[11];
    const float* ln2_offset = (const float*)d_in[12];
    const float* w1 = (const float*)d_in[13];
    const float* b1 = (const float*)d_in[14];
    const float* w2 = (const float*)d_in[15];
    const float* b2 = (const float*)d_in[16];
    float* out = (float*)d_out;

    float *x1, *q, *k, *v, *ctx, *x, *y, *hbuf;
    cudaGetSymbolAddress((void**)&x1,   g_x1);
    cudaGetSymbolAddress((void**)&q,    g_q);
    cudaGetSymbolAddress((void**)&k,    g_k);
    cudaGetSymbolAddress((void**)&v,    g_v);
    cudaGetSymbolAddress((void**)&ctx,  g_ctx);
    cudaGetSymbolAddress((void**)&x,    g_x);
    cudaGetSymbolAddress((void**)&y,    g_y);
    cudaGetSymbolAddress((void**)&hbuf, g_h);

    // 1. LN1
    ln_kernel<<<MM, 128>>>(inputs, ln1_scale, ln1_offset, x1);

    // 2. QKV projections
    dim3 gD(DD / 64, MM / 64);
    gemm_kernel<0><<<gD, 256>>>(x1, wq, bq, nullptr, q, MM, DD, DD);
    gemm_kernel<0><<<gD, 256>>>(x1, wk, bk, nullptr, k, MM, DD, DD);
    gemm_kernel<0><<<gD, 256>>>(x1, wv, bv, nullptr, v, MM, DD, DD);

    // 3. attention
    attn_kernel<<<dim3(TT / 64, BB * HH), 256>>>(q, k, v, ctx);

    // 4. output projection + residual
    gemm_kernel<2><<<gD, 256>>>(ctx, wo, bo, inputs, x, MM, DD, DD);

    // 5. LN2
    ln_kernel<<<MM, 128>>>(x, ln2_scale, ln2_offset, y);

    // 6. FFN up + GELU (tanh approx, JAX default)
    dim3 gF(FF / 64, MM / 64);
    gemm_kernel<1><<<gF, 256>>>(y, w1, b1, nullptr, hbuf, MM, FF, DD);

    // 7. FFN down + residual -> out
    gemm_kernel<2><<<gD, 256>>>(hbuf, w2, b2, x, out, MM, DD, FF);
}

// round 2
// speedup vs baseline: 2.9339x; 2.9339x over previous
#include <cuda_runtime.h>
#include <math.h>

#define BB 2
#define TT 4096
#define DD 512
#define HH 8
#define HK 64
#define FF 2048
#define MM (BB*TT)   // 8192 rows

// ---------------- scratch (no allocs allowed) ----------------
__device__ float g_x1 [MM*DD];
__device__ float g_q  [MM*DD];
__device__ float g_k  [MM*DD];
__device__ float g_v  [MM*DD];
__device__ float g_ctx[MM*DD];
__device__ float g_x  [MM*DD];
__device__ float g_y  [MM*DD];
__device__ float g_h  [MM*FF];

// ---------------- LayerNorm ----------------
__global__ void __launch_bounds__(128) ln_kernel(const float* __restrict__ x,
                                                 const float* __restrict__ sc,
                                                 const float* __restrict__ of,
                                                 float* __restrict__ out) {
    int row = blockIdx.x;
    int tid = threadIdx.x;
    const float4* xr = (const float4*)(x + (size_t)row * DD);
    float4 v = xr[tid];
    float s  = v.x + v.y + v.z + v.w;
    float ss = v.x*v.x + v.y*v.y + v.z*v.z + v.w*v.w;
    #pragma unroll
    for (int o = 16; o > 0; o >>= 1) {
        s  += __shfl_xor_sync(0xffffffffu, s,  o);
        ss += __shfl_xor_sync(0xffffffffu, ss, o);
    }
    __shared__ float s_s[4], s_ss[4];
    int wid = tid >> 5, lane = tid & 31;
    if (lane == 0) { s_s[wid] = s; s_ss[wid] = ss; }
    __syncthreads();
    s  = s_s[0]  + s_s[1]  + s_s[2]  + s_s[3];
    ss = s_ss[0] + s_ss[1] + s_ss[2] + s_ss[3];
    float mean = s * (1.0f / DD);
    float var  = ss * (1.0f / DD) - mean * mean;
    float inv  = rsqrtf(var + 1e-5f);
    float4 scv = ((const float4*)sc)[tid];
    float4 ofv = ((const float4*)of)[tid];
    float4 o;
    o.x = (v.x - mean) * inv * scv.x + ofv.x;
    o.y = (v.y - mean) * inv * scv.y + ofv.y;
    o.z = (v.z - mean) * inv * scv.z + ofv.z;
    o.w = (v.w - mean) * inv * scv.w + ofv.w;
    ((float4*)(out + (size_t)row * DD))[tid] = o;
}

// ---------------- GEMM core: 128x128 tile, 8x8 microtile, 256 thr ----------------
__device__ __forceinline__ float gelu_tanh(float x) {
    float x3 = x * x * x;
    return 0.5f * x * (1.0f + tanhf(0.7978845608028654f * (x + 0.044715f * x3)));
}

// EPI: 0 = bias, 1 = bias+gelu, 2 = bias+residual
template <int EPI>
__device__ __forceinline__ void gemm_core(const float* __restrict__ A,
                                          const float* __restrict__ B,
                                          const float* __restrict__ bias,
                                          const float* __restrict__ res,
                                          float* __restrict__ C,
                                          int N, int Kd) {
    __shared__ float As[2][8][132];   // [k][m], padded stride 132 (16B-aligned, conflict-free)
    __shared__ float Bs[2][8][128];   // [k][n]

    const int tid  = threadIdx.x;
    const int lane = tid & 31, warp = tid >> 5;
    const int wm = warp >> 1, wn = warp & 1;      // warps 4x2
    const int lm = lane >> 3, ln = lane & 7;      // lanes 4x8
    const int tm = wm * 32 + lm * 8;              // 8 consecutive m rows
    const int tn = wn * 64 + ln * 4;              // n cols tn..tn+3 and tn+32..tn+35
    const int m0 = blockIdx.y * 128;
    const int n0 = blockIdx.x * 128;

    const int arow = tid >> 1;                    // 0..127
    const int acol = (tid & 1) * 4;               // 0 or 4
    const int brow = tid >> 5;                    // 0..7
    const int bcol = (tid & 31) * 4;              // 0..124

    const float* Ag = A + (size_t)(m0 + arow) * Kd + acol;
    const float* Bg = B + (size_t)brow * N + n0 + bcol;

    float acc[8][8];
    #pragma unroll
    for (int i = 0; i < 8; i++)
        #pragma unroll
        for (int j = 0; j < 8; j++) acc[i][j] = 0.0f;

    // preload k-tile 0
    {
        float4 av = *(const float4*)Ag;
        float4 bv = *(const float4*)Bg;
        As[0][acol+0][arow] = av.x; As[0][acol+1][arow] = av.y;
        As[0][acol+2][arow] = av.z; As[0][acol+3][arow] = av.w;
        *(float4*)&Bs[0][brow][bcol] = bv;
    }
    __syncthreads();

    const int niter = Kd >> 3;
    for (int it = 0; it < niter; it++) {
        float4 an, bn;
        const bool more = (it + 1 < niter);
        if (more) {
            an = *(const float4*)(Ag + (it + 1) * 8);
            bn = *(const float4*)(Bg + (size_t)(it + 1) * 8 * N);
        }
        const int bsel = it & 1;
        #pragma unroll
        for (int kk = 0; kk < 8; kk++) {
            float4 a0 = *(const float4*)&As[bsel][kk][tm];
            float4 a1 = *(const float4*)&As[bsel][kk][tm + 4];
            float4 b0 = *(const float4*)&Bs[bsel][kk][tn];
            float4 b1 = *(const float4*)&Bs[bsel][kk][tn + 32];
            float am[8] = {a0.x,a0.y,a0.z,a0.w,a1.x,a1.y,a1.z,a1.w};
            float bm[8] = {b0.x,b0.y,b0.z,b0.w,b1.x,b1.y,b1.z,b1.w};
            #pragma unroll
            for (int i = 0; i < 8; i++)
                #pragma unroll
                for (int j = 0; j < 8; j++)
                    acc[i][j] += am[i] * bm[j];
        }
        if (more) {
            const int ns = bsel ^ 1;
            As[ns][acol+0][arow] = an.x; As[ns][acol+1][arow] = an.y;
            As[ns][acol+2][arow] = an.z; As[ns][acol+3][arow] = an.w;
            *(float4*)&Bs[ns][brow][bcol] = bn;
        }
        __syncthreads();
    }

    // epilogue
    float4 bz0 = *(const float4*)&bias[n0 + tn];
    float4 bz1 = *(const float4*)&bias[n0 + tn + 32];
    #pragma unroll
    for (int i = 0; i < 8; i++) {
        const int row = m0 + tm + i;
        float o[8];
        o[0] = acc[i][0] + bz0.x; o[1] = acc[i][1] + bz0.y;
        o[2] = acc[i][2] + bz0.z; o[3] = acc[i][3] + bz0.w;
        o[4] = acc[i][4] + bz1.x; o[5] = acc[i][5] + bz1.y;
        o[6] = acc[i][6] + bz1.z; o[7] = acc[i][7] + bz1.w;
        if (EPI == 1) {
            #pragma unroll
            for (int j = 0; j < 8; j++) o[j] = gelu_tanh(o[j]);
        }
        if (EPI == 2) {
            float4 r0 = *(const float4*)&res[(size_t)row * N + n0 + tn];
            float4 r1 = *(const float4*)&res[(size_t)row * N + n0 + tn + 32];
            o[0] += r0.x; o[1] += r0.y; o[2] += r0.z; o[3] += r0.w;
            o[4] += r1.x; o[5] += r1.y; o[6] += r1.z; o[7] += r1.w;
        }
        float4 w0 = {o[0], o[1], o[2], o[3]};
        float4 w1 = {o[4], o[5], o[6], o[7]};
        *(float4*)&C[(size_t)row * N + n0 + tn]      = w0;
        *(float4*)&C[(size_t)row * N + n0 + tn + 32] = w1;
    }
}

template <int EPI>
__global__ void __launch_bounds__(256, 2) gemm_kernel(const float* __restrict__ A,
                                                      const float* __restrict__ B,
                                                      const float* __restrict__ bias,
                                                      const float* __restrict__ res,
                                                      float* __restrict__ C,
                                                      int N, int Kd) {
    gemm_core<EPI>(A, B, bias, res, C, N, Kd);
}

// fused QKV: blockIdx.z selects projection
__global__ void __launch_bounds__(256, 2) qkv_kernel(const float* __restrict__ A,
                                                     const float* __restrict__ wq, const float* __restrict__ bq, float* __restrict__ q,
                                                     const float* __restrict__ wk, const float* __restrict__ bk, float* __restrict__ k,
                                                     const float* __restrict__ wv, const float* __restrict__ bv, float* __restrict__ v) {
    const float* W; const float* bz; float* O;
    if (blockIdx.z == 0)      { W = wq; bz = bq; O = q; }
    else if (blockIdx.z == 1) { W = wk; bz = bk; O = k; }
    else                      { W = wv; bz = bv; O = v; }
    gemm_core<0>(A, W, bz, nullptr, O, DD, DD);
}

// ---------------- Flash attention: 128q block, 64-key tiles, 8x4 microtiles ----------------
// smem: Qs[128][64] | Ks[64][64] swz | Vs[64][64] swz | Ps[128][64]  = 96 KB dynamic
__global__ void __launch_bounds__(256) attn_kernel(const float* __restrict__ Q,
                                                   const float* __restrict__ Kg,
                                                   const float* __restrict__ Vg,
                                                   float* __restrict__ Og) {
    extern __shared__ float sm[];
    float* Qs = sm;                 // [128][64]
    float* Ks = Qs + 128 * 64;      // [64][64], chunk-swizzled
    float* Vs = Ks + 64 * 64;       // [64][64], chunk-swizzled
    float* Ps = Vs + 64 * 64;       // [128][64]

    const int tid = threadIdx.x;
    const int tx = tid & 15, ty = tid >> 4;
    const int b = blockIdx.y >> 3, h = blockIdx.y & 7;
    const int qt = blockIdx.x * 128;

    const float* Qb = Q  + ((size_t)b * TT) * DD + h * HK;
    const float* Kb = Kg + ((size_t)b * TT) * DD + h * HK;
    const float* Vb = Vg + ((size_t)b * TT) * DD + h * HK;

    // load Q tile (pre-scaled by 1/sqrt(K))
    #pragma unroll
    for (int itq = 0; itq < 8; itq++) {
        int idx = tid + itq * 256;
        int r = idx >> 4, c = idx & 15;
        float4 qv = *(const float4*)(Qb + (size_t)(qt + r) * DD + c * 4);
        qv.x *= 0.125f; qv.y *= 0.125f; qv.z *= 0.125f; qv.w *= 0.125f;
        *(float4*)&Qs[r * 64 + c * 4] = qv;
    }

    float m[8], l[8], o[8][4];
    #pragma unroll
    for (int i = 0; i < 8; i++) {
        m[i] = -1e30f; l[i] = 0.0f;
        o[i][0] = o[i][1] = o[i][2] = o[i][3] = 0.0f;
    }

    for (int kt = 0; kt < TT; kt += 64) {
        __syncthreads();   // prior reads of Ks/Vs done (also covers initial Qs visibility)
        #pragma unroll
        for (int itl = 0; itl < 4; itl++) {
            int idx = tid + itl * 256;
            int r = idx >> 4, c = idx & 15;
            int cs = c ^ ((r >> 2) & 15);   // XOR chunk swizzle
            *(float4*)&Ks[r * 64 + cs * 4] = *(const float4*)(Kb + (size_t)(kt + r) * DD + c * 4);
            *(float4*)&Vs[r * 64 + cs * 4] = *(const float4*)(Vb + (size_t)(kt + r) * DD + c * 4);
        }
        __syncthreads();

        // ---- S = Q K^T : thread tile 8q x 4k ----
        float s[8][4];
        #pragma unroll
        for (int i = 0; i < 8; i++) { s[i][0]=0.f; s[i][1]=0.f; s[i][2]=0.f; s[i][3]=0.f; }

        #pragma unroll 4
        for (int cd = 0; cd < 16; cd++) {
            float4 kv[4];
            #pragma unroll
            for (int j = 0; j < 4; j++)
                kv[j] = *(const float4*)&Ks[(tx * 4 + j) * 64 + ((cd ^ tx) & 15) * 4];
            #pragma unroll
            for (int i = 0; i < 8; i++) {
                float4 qv = *(const float4*)&Qs[(ty * 8 + i) * 64 + cd * 4];
                #pragma unroll
                for (int j = 0; j < 4; j++)
                    s[i][j] += qv.x * kv[j].x + qv.y * kv[j].y + qv.z * kv[j].z + qv.w * kv[j].w;
            }
        }

        // ---- online softmax (16 tx lanes share each q row) ----
        #pragma unroll
        for (int i = 0; i < 8; i++) {
            float tmx = fmaxf(fmaxf(s[i][0], s[i][1]), fmaxf(s[i][2], s[i][3]));
            #pragma unroll
            for (int off = 1; off < 16; off <<= 1)
                tmx = fmaxf(tmx, __shfl_xor_sync(0xffffffffu, tmx, off));
            float nm = fmaxf(m[i], tmx);
            float alpha = __expf(m[i] - nm);
            m[i] = nm;
            float p0 = __expf(s[i][0] - nm);
            float p1 = __expf(s[i][1] - nm);
            float p2 = __expf(s[i][2] - nm);
            float p3 = __expf(s[i][3] - nm);
            float rs = p0 + p1 + p2 + p3;
            #pragma unroll
            for (int off = 1; off < 16; off <<= 1)
                rs += __shfl_xor_sync(0xffffffffu, rs, off);
            l[i] = l[i] * alpha + rs;
            o[i][0] *= alpha; o[i][1] *= alpha; o[i][2] *= alpha; o[i][3] *= alpha;
            float4 pv = {p0, p1, p2, p3};
            *(float4*)&Ps[(ty * 8 + i) * 64 + tx * 4] = pv;
        }
        __syncwarp();   // P rows are produced/consumed within one warp

        // ---- O += P V : thread tile 8q x 4d ----
        #pragma unroll 4
        for (int kc = 0; kc < 16; kc++) {
            float4 vv[4];
            #pragma unroll
            for (int j = 0; j < 4; j++)
                vv[j] = *(const float4*)&Vs[(kc * 4 + j) * 64 + ((tx ^ kc) & 15) * 4];
            #pragma unroll
            for (int i = 0; i < 8; i++) {
                float4 pv = *(const float4*)&Ps[(ty * 8 + i) * 64 + kc * 4];
                o[i][0] += pv.x * vv[0].x + pv.y * vv[1].x + pv.z * vv[2].x + pv.w * vv[3].x;
                o[i][1] += pv.x * vv[0].y + pv.y * vv[1].y + pv.z * vv[2].y + pv.w * vv[3].y;
                o[i][2] += pv.x * vv[0].z + pv.y * vv[1].z + pv.z * vv[2].z + pv.w * vv[3].z;
                o[i][3] += pv.x * vv[0].w + pv.y * vv[1].w + pv.z * vv[2].w + pv.w * vv[3].w;
            }
        }
    }

    #pragma unroll
    for (int i = 0; i < 8; i++) {
        float inv = 1.0f / l[i];
        float4 ov = {o[i][0]*inv, o[i][1]*inv, o[i][2]*inv, o[i][3]*inv};
        *(float4*)(Og + ((size_t)b * TT + qt + ty * 8 + i) * DD + h * HK + tx * 4) = ov;
    }
}

// ---------------- launch ----------------
extern "C" void kernel_launch(void* const* d_in, const int* in_sizes, int n_in,
                              void* d_out, int out_size) {
    const float* inputs     = (const float*)d_in[0];
    const float* ln1_scale  = (const float*)d_in[1];
    const float* ln1_offset = (const float*)d_in[2];
    const float* wq = (const float*)d_in[3];
    const float* bq = (const float*)d_in[4];
    const float* wk = (const float*)d_in[5];
    const float* bk = (const float*)d_in[6];
    const float* wv = (const float*)d_in[7];
    const float* bv = (const float*)d_in[8];
    const float* wo = (const float*)d_in[9];
    const float* bo = (const float*)d_in[10];
    const float* ln2_scale  = (const float*)d_in[11];
    const float* ln2_offset = (const float*)d_in[12];
    const float* w1 = (const float*)d_in[13];
    const float* b1 = (const float*)d_in[14];
    const float* w2 = (const float*)d_in[15];
    const float* b2 = (const float*)d_in[16];
    float* out = (float*)d_out;

    float *x1, *q, *k, *v, *ctx, *x, *y, *hbuf;
    cudaGetSymbolAddress((void**)&x1,   g_x1);
    cudaGetSymbolAddress((void**)&q,    g_q);
    cudaGetSymbolAddress((void**)&k,    g_k);
    cudaGetSymbolAddress((void**)&v,    g_v);
    cudaGetSymbolAddress((void**)&ctx,  g_ctx);
    cudaGetSymbolAddress((void**)&x,    g_x);
    cudaGetSymbolAddress((void**)&y,    g_y);
    cudaGetSymbolAddress((void**)&hbuf, g_h);

    cudaFuncSetAttribute(attn_kernel, cudaFuncAttributeMaxDynamicSharedMemorySize, 98304);

    // 1. LN1
    ln_kernel<<<MM, 128>>>(inputs, ln1_scale, ln1_offset, x1);

    // 2. fused QKV projections (one launch, 3 z-slices)
    qkv_kernel<<<dim3(DD/128, MM/128, 3), 256>>>(x1, wq, bq, q, wk, bk, k, wv, bv, v);

    // 3. flash attention
    attn_kernel<<<dim3(TT/128, BB*HH), 256, 98304>>>(q, k, v, ctx);

    // 4. output projection + residual
    gemm_kernel<2><<<dim3(DD/128, MM/128), 256>>>(ctx, wo, bo, inputs, x, DD, DD);

    // 5. LN2
    ln_kernel<<<MM, 128>>>(x, ln2_scale, ln2_offset, y);

    // 6. FFN up + GELU
    gemm_kernel<1><<<dim3(FF/128, MM/128), 256>>>(y, w1, b1, nullptr, hbuf, FF, DD);

    // 7. FFN down + residual -> out
    gemm_kernel<2><<<dim3(DD/128, MM/128), 256>>>(hbuf, w2, b2, x, out, DD, FF);
}

// round 4
// speedup vs baseline: 3.3431x; 1.1395x over previous
#include <cuda_runtime.h>
#include <cuda_bf16.h>
#include <math.h>
#include <stdint.h>

#define BB 2
#define TT 4096
#define DD 512
#define HH 8
#define HK 64
#define FF 2048
#define MM (BB*TT)   // 8192 rows

// ---------------- scratch (no allocs allowed) ----------------
__device__ float g_x1 [MM*DD];
__device__ float g_q  [MM*DD];
__device__ float g_k  [MM*DD];
__device__ float g_v  [MM*DD];
__device__ float g_ctx[MM*DD];
__device__ float g_x  [MM*DD];
__device__ float g_y  [MM*DD];
__device__ float g_h  [MM*FF];
// transposed weights [N][K]
__device__ float g_wtq[DD*DD];
__device__ float g_wtk[DD*DD];
__device__ float g_wtv[DD*DD];
__device__ float g_wto[DD*DD];
__device__ float g_wt1[FF*DD];
__device__ float g_wt2[DD*FF];

// ================= helpers (sm_80-era only: compute_103-safe) =================
__device__ __forceinline__ uint32_t smem_u32(const void* p) {
    uint32_t a;
    asm("{ .reg .u64 t; cvta.to.shared.u64 t, %1; cvt.u32.u64 %0, t; }" : "=r"(a) : "l"(p));
    return a;
}
__device__ __forceinline__ void ldm4(uint32_t* r, uint32_t addr) {
    asm volatile("ldmatrix.sync.aligned.m8n8.x4.shared.b16 {%0,%1,%2,%3}, [%4];"
        : "=r"(r[0]), "=r"(r[1]), "=r"(r[2]), "=r"(r[3]) : "r"(addr));
}
__device__ __forceinline__ void mma_bf16(float* c, const uint32_t* a, uint32_t b0, uint32_t b1) {
    asm volatile("mma.sync.aligned.m16n8k16.row.col.f32.bf16.bf16.f32 "
        "{%0,%1,%2,%3}, {%4,%5,%6,%7}, {%8,%9}, {%0,%1,%2,%3};"
        : "+f"(c[0]), "+f"(c[1]), "+f"(c[2]), "+f"(c[3])
        : "r"(a[0]), "r"(a[1]), "r"(a[2]), "r"(a[3]), "r"(b0), "r"(b1));
}
#define STS64U(addr, r0, r1) \
    asm volatile("st.shared.v2.b32 [%0], {%1,%2};" :: "r"(addr), "r"(r0), "r"(r1) : "memory")

// split fp32 pair -> packed bf16 hi and lo words
__device__ __forceinline__ void split2(float x0, float x1, uint32_t& hi, uint32_t& lo) {
    __nv_bfloat16 h0 = __float2bfloat16_rn(x0);
    __nv_bfloat16 h1 = __float2bfloat16_rn(x1);
    __nv_bfloat16 l0 = __float2bfloat16_rn(x0 - __bfloat162float(h0));
    __nv_bfloat16 l1 = __float2bfloat16_rn(x1 - __bfloat162float(h1));
    hi = (uint32_t)__bfloat16_as_ushort(h0) | ((uint32_t)__bfloat16_as_ushort(h1) << 16);
    lo = (uint32_t)__bfloat16_as_ushort(l0) | ((uint32_t)__bfloat16_as_ushort(l1) << 16);
}

// ---------------- LayerNorm ----------------
__global__ void __launch_bounds__(128) ln_kernel(const float* __restrict__ x,
                                                 const float* __restrict__ sc,
                                                 const float* __restrict__ of,
                                                 float* __restrict__ out) {
    int row = blockIdx.x;
    int tid = threadIdx.x;
    const float4* xr = (const float4*)(x + (size_t)row * DD);
    float4 v = xr[tid];
    float s  = v.x + v.y + v.z + v.w;
    float ss = v.x*v.x + v.y*v.y + v.z*v.z + v.w*v.w;
    #pragma unroll
    for (int o = 16; o > 0; o >>= 1) {
        s  += __shfl_xor_sync(0xffffffffu, s,  o);
        ss += __shfl_xor_sync(0xffffffffu, ss, o);
    }
    __shared__ float s_s[4], s_ss[4];
    int wid = tid >> 5, lane = tid & 31;
    if (lane == 0) { s_s[wid] = s; s_ss[wid] = ss; }
    __syncthreads();
    s  = s_s[0]  + s_s[1]  + s_s[2]  + s_s[3];
    ss = s_ss[0] + s_ss[1] + s_ss[2] + s_ss[3];
    float mean = s * (1.0f / DD);
    float var  = ss * (1.0f / DD) - mean * mean;
    float inv  = rsqrtf(var + 1e-5f);
    float4 scv = ((const float4*)sc)[tid];
    float4 ofv = ((const float4*)of)[tid];
    float4 o;
    o.x = (v.x - mean) * inv * scv.x + ofv.x;
    o.y = (v.y - mean) * inv * scv.y + ofv.y;
    o.z = (v.z - mean) * inv * scv.z + ofv.z;
    o.w = (v.w - mean) * inv * scv.w + ofv.w;
    ((float4*)(out + (size_t)row * DD))[tid] = o;
}

// ---------------- weight transpose: dst[C][R] = src[R][C] ----------------
__global__ void __launch_bounds__(256) transpose_kernel(const float* __restrict__ S,
                                                        float* __restrict__ D, int R, int C) {
    __shared__ float t[32][33];
    int bx = blockIdx.x * 32, by = blockIdx.y * 32;
    int x = threadIdx.x & 31, y = (threadIdx.x >> 5) * 4;
    #pragma unroll
    for (int i = 0; i < 4; i++)
        t[y + i][x] = S[(size_t)(by + y + i) * C + bx + x];
    __syncthreads();
    #pragma unroll
    for (int i = 0; i < 4; i++)
        D[(size_t)(bx + y + i) * R + by + x] = t[x][y + i];
}

// ---------------- bf16x3 mma.sync GEMM ----------------
// C[M,N] = A[M,K] @ Bt[N,K]^T + bias (+epilogue). 128x128 CTA tile, 256 thr.
// Precision: bf16 hi/lo split, 3 MMAs per product (hi*hi + hi*lo + lo*hi).
__device__ __forceinline__ float gelu_tanh(float x) {
    float x3 = x * x * x;
    return 0.5f * x * (1.0f + tanhf(0.7978845608028654f * (x + 0.044715f * x3)));
}

#define RS 40   // smem row stride in bf16 elements (80 bytes: conflict-free ldmatrix)

template <int EPI>   // 0 bias, 1 bias+gelu, 2 bias+residual
__device__ __forceinline__ void mma_gemm_core(const float* __restrict__ A,
                                              const float* __restrict__ Bt,
                                              const float* __restrict__ bias,
                                              const float* __restrict__ res,
                                              float* __restrict__ C,
                                              int N, int Kd) {
    __shared__ __align__(16) __nv_bfloat16 sAh[128 * RS];
    __shared__ __align__(16) __nv_bfloat16 sAl[128 * RS];
    __shared__ __align__(16) __nv_bfloat16 sBh[128 * RS];
    __shared__ __align__(16) __nv_bfloat16 sBl[128 * RS];
    const uint32_t aAh = smem_u32(sAh), aAl = smem_u32(sAl);
    const uint32_t aBh = smem_u32(sBh), aBl = smem_u32(sBl);

    const int tid  = threadIdx.x;
    const int lane = tid & 31, warp = tid >> 5;
    const int wm = warp >> 1, wn = warp & 1;
    const int m0 = blockIdx.y * 128;
    const int n0 = blockIdx.x * 128;

    // ldmatrix per-lane offsets
    const int g = lane >> 3, lr = lane & 7;
    uint32_t offA[2][2], offB[4][2];
    #pragma unroll
    for (int t = 0; t < 2; t++) {
        int row = wm * 32 + t * 16 + (g & 1) * 8 + lr;
        #pragma unroll
        for (int ks = 0; ks < 2; ks++)
            offA[t][ks] = (uint32_t)(row * (RS * 2) + (ks * 16 + (g >> 1) * 8) * 2);
    }
    #pragma unroll
    for (int p = 0; p < 4; p++) {
        int row = wn * 64 + p * 16 + (g >> 1) * 8 + lr;
        #pragma unroll
        for (int ks = 0; ks < 2; ks++)
            offB[p][ks] = (uint32_t)(row * (RS * 2) + (ks * 16 + (g & 1) * 8) * 2);
    }

    // gmem load mapping: idx = tid + i*256 over 1024; rr = idx>>3, c4 = (idx&7)*4
    const int rr = tid >> 3;              // base row for i=0 (rows advance by 32 per i)
    const int c4 = (tid & 7) * 4;
    const uint32_t sOff = (uint32_t)(rr * (RS * 2) + c4 * 2);

    float acc[2][8][4];
    #pragma unroll
    for (int mt = 0; mt < 2; mt++)
        #pragma unroll
        for (int nt = 0; nt < 8; nt++)
            #pragma unroll
            for (int j = 0; j < 4; j++) acc[mt][nt][j] = 0.0f;

    float4 av[4], bv[4];
    #pragma unroll
    for (int i = 0; i < 4; i++) {
        av[i] = *(const float4*)(A  + (size_t)(m0 + rr + i * 32) * Kd + c4);
        bv[i] = *(const float4*)(Bt + (size_t)(n0 + rr + i * 32) * Kd + c4);
    }

    const int nchunk = Kd >> 5;
    for (int ck = 0; ck < nchunk; ck++) {
        __syncthreads();   // previous compute done reading smem
        #pragma unroll
        for (int i = 0; i < 4; i++) {
            uint32_t so = sOff + (uint32_t)(i * 32 * RS * 2);
            uint32_t h0, l0, h1, l1;
            split2(av[i].x, av[i].y, h0, l0);
            split2(av[i].z, av[i].w, h1, l1);
            STS64U(aAh + so, h0, h1);
            STS64U(aAl + so, l0, l1);
            split2(bv[i].x, bv[i].y, h0, l0);
            split2(bv[i].z, bv[i].w, h1, l1);
            STS64U(aBh + so, h0, h1);
            STS64U(aBl + so, l0, l1);
        }
        __syncthreads();
        if (ck + 1 < nchunk) {
            const int k0 = (ck + 1) * 32;
            #pragma unroll
            for (int i = 0; i < 4; i++) {
                av[i] = *(const float4*)(A  + (size_t)(m0 + rr + i * 32) * Kd + k0 + c4);
                bv[i] = *(const float4*)(Bt + (size_t)(n0 + rr + i * 32) * Kd + k0 + c4);
            }
        }
        #pragma unroll
        for (int ks = 0; ks < 2; ks++) {
            uint32_t ah[2][4], al[2][4];
            ldm4(ah[0], aAh + offA[0][ks]);
            ldm4(ah[1], aAh + offA[1][ks]);
            ldm4(al[0], aAl + offA[0][ks]);
            ldm4(al[1], aAl + offA[1][ks]);
            uint32_t bh[4][4], bl[4][4];
            #pragma unroll
            for (int p = 0; p < 4; p++) {
                ldm4(bh[p], aBh + offB[p][ks]);
                ldm4(bl[p], aBl + offB[p][ks]);
            }
            #pragma unroll
            for (int mt = 0; mt < 2; mt++)
                #pragma unroll
                for (int nt = 0; nt < 8; nt++) {
                    uint32_t bh0 = bh[nt >> 1][(nt & 1) * 2], bh1 = bh[nt >> 1][(nt & 1) * 2 + 1];
                    uint32_t bl0 = bl[nt >> 1][(nt & 1) * 2], bl1 = bl[nt >> 1][(nt & 1) * 2 + 1];
                    mma_bf16(acc[mt][nt], ah[mt], bh0, bh1);
                    mma_bf16(acc[mt][nt], ah[mt], bl0, bl1);
                    mma_bf16(acc[mt][nt], al[mt], bh0, bh1);
                }
        }
    }

    // epilogue: fragment (row = lane>>2 [+8], col = (lane&3)*2)
    const int erow = m0 + wm * 32 + (lane >> 2);
    const int ecol = n0 + wn * 64 + (lane & 3) * 2;
    #pragma unroll
    for (int mt = 0; mt < 2; mt++) {
        #pragma unroll
        for (int nt = 0; nt < 8; nt++) {
            const int col = ecol + nt * 8;
            float2 bz = *(const float2*)&bias[col];
            float v0 = acc[mt][nt][0] + bz.x;
            float v1 = acc[mt][nt][1] + bz.y;
            float v2 = acc[mt][nt][2] + bz.x;
            float v3 = acc[mt][nt][3] + bz.y;
            int r0 = erow + mt * 16, r1 = r0 + 8;
            if (EPI == 1) {
                v0 = gelu_tanh(v0); v1 = gelu_tanh(v1);
                v2 = gelu_tanh(v2); v3 = gelu_tanh(v3);
            }
            if (EPI == 2) {
                float2 ra = *(const float2*)&res[(size_t)r0 * N + col];
                float2 rb = *(const float2*)&res[(size_t)r1 * N + col];
                v0 += ra.x; v1 += ra.y; v2 += rb.x; v3 += rb.y;
            }
            float2 w0 = {v0, v1}, w1 = {v2, v3};
            *(float2*)&C[(size_t)r0 * N + col] = w0;
            *(float2*)&C[(size_t)r1 * N + col] = w1;
        }
    }
}

template <int EPI>
__global__ void __launch_bounds__(256, 1) mma_gemm_kernel(const float* __restrict__ A,
                                                          const float* __restrict__ Bt,
                                                          const float* __restrict__ bias,
                                                          const float* __restrict__ res,
                                                          float* __restrict__ C,
                                                          int N, int Kd) {
    mma_gemm_core<EPI>(A, Bt, bias, res, C, N, Kd);
}

__global__ void __launch_bounds__(256, 1) mma_qkv_kernel(const float* __restrict__ A,
        const float* __restrict__ wtq, const float* __restrict__ bq, float* __restrict__ q,
        const float* __restrict__ wtk, const float* __restrict__ bk, float* __restrict__ k,
        const float* __restrict__ wtv, const float* __restrict__ bv, float* __restrict__ v) {
    const float* W; const float* bz; float* O;
    if (blockIdx.z == 0)      { W = wtq; bz = bq; O = q; }
    else if (blockIdx.z == 1) { W = wtk; bz = bk; O = k; }
    else                      { W = wtv; bz = bv; O = v; }
    mma_gemm_core<0>(A, W, bz, nullptr, O, DD, DD);
}

// ---------------- Flash attention (scalar, unchanged from R2) ----------------
__global__ void __launch_bounds__(256) attn_kernel(const float* __restrict__ Q,
                                                   const float* __restrict__ Kg,
                                                   const float* __restrict__ Vg,
                                                   float* __restrict__ Og) {
    extern __shared__ float sm[];
    float* Qs = sm;
    float* Ks = Qs + 128 * 64;
    float* Vs = Ks + 64 * 64;
    float* Ps = Vs + 64 * 64;

    const int tid = threadIdx.x;
    const int tx = tid & 15, ty = tid >> 4;
    const int b = blockIdx.y >> 3, h = blockIdx.y & 7;
    const int qt = blockIdx.x * 128;

    const float* Qb = Q  + ((size_t)b * TT) * DD + h * HK;
    const float* Kb = Kg + ((size_t)b * TT) * DD + h * HK;
    const float* Vb = Vg + ((size_t)b * TT) * DD + h * HK;

    #pragma unroll
    for (int itq = 0; itq < 8; itq++) {
        int idx = tid + itq * 256;
        int r = idx >> 4, c = idx & 15;
        float4 qv = *(const float4*)(Qb + (size_t)(qt + r) * DD + c * 4);
        qv.x *= 0.125f; qv.y *= 0.125f; qv.z *= 0.125f; qv.w *= 0.125f;
        *(float4*)&Qs[r * 64 + c * 4] = qv;
    }

    float m[8], l[8], o[8][4];
    #pragma unroll
    for (int i = 0; i < 8; i++) {
        m[i] = -1e30f; l[i] = 0.0f;
        o[i][0] = o[i][1] = o[i][2] = o[i][3] = 0.0f;
    }

    for (int kt = 0; kt < TT; kt += 64) {
        __syncthreads();
        #pragma unroll
        for (int itl = 0; itl < 4; itl++) {
            int idx = tid + itl * 256;
            int r = idx >> 4, c = idx & 15;
            int cs = c ^ ((r >> 2) & 15);
            *(float4*)&Ks[r * 64 + cs * 4] = *(const float4*)(Kb + (size_t)(kt + r) * DD + c * 4);
            *(float4*)&Vs[r * 64 + cs * 4] = *(const float4*)(Vb + (size_t)(kt + r) * DD + c * 4);
        }
        __syncthreads();

        float s[8][4];
        #pragma unroll
        for (int i = 0; i < 8; i++) { s[i][0]=0.f; s[i][1]=0.f; s[i][2]=0.f; s[i][3]=0.f; }

        #pragma unroll 4
        for (int cd = 0; cd < 16; cd++) {
            float4 kv[4];
            #pragma unroll
            for (int j = 0; j < 4; j++)
                kv[j] = *(const float4*)&Ks[(tx * 4 + j) * 64 + ((cd ^ tx) & 15) * 4];
            #pragma unroll
            for (int i = 0; i < 8; i++) {
                float4 qv = *(const float4*)&Qs[(ty * 8 + i) * 64 + cd * 4];
                #pragma unroll
                for (int j = 0; j < 4; j++)
                    s[i][j] += qv.x * kv[j].x + qv.y * kv[j].y + qv.z * kv[j].z + qv.w * kv[j].w;
            }
        }

        #pragma unroll
        for (int i = 0; i < 8; i++) {
            float tmx = fmaxf(fmaxf(s[i][0], s[i][1]), fmaxf(s[i][2], s[i][3]));
            #pragma unroll
            for (int off = 1; off < 16; off <<= 1)
                tmx = fmaxf(tmx, __shfl_xor_sync(0xffffffffu, tmx, off));
            float nm = fmaxf(m[i], tmx);
            float alpha = __expf(m[i] - nm);
            m[i] = nm;
            float p0 = __expf(s[i][0] - nm);
            float p1 = __expf(s[i][1] - nm);
            float p2 = __expf(s[i][2] - nm);
            float p3 = __expf(s[i][3] - nm);
            float rs = p0 + p1 + p2 + p3;
            #pragma unroll
            for (int off = 1; off < 16; off <<= 1)
                rs += __shfl_xor_sync(0xffffffffu, rs, off);
            l[i] = l[i] * alpha + rs;
            o[i][0] *= alpha; o[i][1] *= alpha; o[i][2] *= alpha; o[i][3] *= alpha;
            float4 pv = {p0, p1, p2, p3};
            *(float4*)&Ps[(ty * 8 + i) * 64 + tx * 4] = pv;
        }
        __syncwarp();

        #pragma unroll 4
        for (int kc = 0; kc < 16; kc++) {
            float4 vv[4];
            #pragma unroll
            for (int j = 0; j < 4; j++)
                vv[j] = *(const float4*)&Vs[(kc * 4 + j) * 64 + ((tx ^ kc) & 15) * 4];
            #pragma unroll
            for (int i = 0; i < 8; i++) {
                float4 pv = *(const float4*)&Ps[(ty * 8 + i) * 64 + kc * 4];
                o[i][0] += pv.x * vv[0].x + pv.y * vv[1].x + pv.z * vv[2].x + pv.w * vv[3].x;
                o[i][1] += pv.x * vv[0].y + pv.y * vv[1].y + pv.z * vv[2].y + pv.w * vv[3].y;
                o[i][2] += pv.x * vv[0].z + pv.y * vv[1].z + pv.z * vv[2].z + pv.w * vv[3].z;
                o[i][3] += pv.x * vv[0].w + pv.y * vv[1].w + pv.z * vv[2].w + pv.w * vv[3].w;
            }
        }
    }

    #pragma unroll
    for (int i = 0; i < 8; i++) {
        float inv = 1.0f / l[i];
        float4 ov = {o[i][0]*inv, o[i][1]*inv, o[i][2]*inv, o[i][3]*inv};
        *(float4*)(Og + ((size_t)b * TT + qt + ty * 8 + i) * DD + h * HK + tx * 4) = ov;
    }
}

// ---------------- launch ----------------
extern "C" void kernel_launch(void* const* d_in, const int* in_sizes, int n_in,
                              void* d_out, int out_size) {
    const float* inputs     = (const float*)d_in[0];
    const float* ln1_scale  = (const float*)d_in[1];
    const float* ln1_offset = (const float*)d_in[2];
    const float* wq = (const float*)d_in[3];
    const float* bq = (const float*)d_in[4];
    const float* wk = (const float*)d_in[5];
    const float* bk = (const float*)d_in[6];
    const float* wv = (const float*)d_in[7];
    const float* bv = (const float*)d_in[8];
    const float* wo = (const float*)d_in[9];
    const float* bo = (const float*)d_in[10];
    const float* ln2_scale  = (const float*)d_in[11];
    const float* ln2_offset = (const float*)d_in[12];
    const float* w1 = (const float*)d_in[13];
    const float* b1 = (const float*)d_in[14];
    const float* w2 = (const float*)d_in[15];
    const float* b2 = (const float*)d_in[16];
    float* out = (float*)d_out;

    float *x1, *q, *k, *v, *ctx, *x, *y, *hbuf;
    float *wtq, *wtk, *wtv, *wto, *wt1, *wt2;
    cudaGetSymbolAddress((void**)&x1,   g_x1);
    cudaGetSymbolAddress((void**)&q,    g_q);
    cudaGetSymbolAddress((void**)&k,    g_k);
    cudaGetSymbolAddress((void**)&v,    g_v);
    cudaGetSymbolAddress((void**)&ctx,  g_ctx);
    cudaGetSymbolAddress((void**)&x,    g_x);
    cudaGetSymbolAddress((void**)&y,    g_y);
    cudaGetSymbolAddress((void**)&hbuf, g_h);
    cudaGetSymbolAddress((void**)&wtq,  g_wtq);
    cudaGetSymbolAddress((void**)&wtk,  g_wtk);
    cudaGetSymbolAddress((void**)&wtv,  g_wtv);
    cudaGetSymbolAddress((void**)&wto,  g_wto);
    cudaGetSymbolAddress((void**)&wt1,  g_wt1);
    cudaGetSymbolAddress((void**)&wt2,  g_wt2);

    cudaFuncSetAttribute(attn_kernel, cudaFuncAttributeMaxDynamicSharedMemorySize, 98304);

    // 0. weight transposes ([K,N] -> [N,K])
    transpose_kernel<<<dim3(DD/32, DD/32), 256>>>(wq, wtq, DD, DD);
    transpose_kernel<<<dim3(DD/32, DD/32), 256>>>(wk, wtk, DD, DD);
    transpose_kernel<<<dim3(DD/32, DD/32), 256>>>(wv, wtv, DD, DD);
    transpose_kernel<<<dim3(DD/32, DD/32), 256>>>(wo, wto, DD, DD);
    transpose_kernel<<<dim3(FF/32, DD/32), 256>>>(w1, wt1, DD, FF);
    transpose_kernel<<<dim3(DD/32, FF/32), 256>>>(w2, wt2, FF, DD);

    // 1. LN1
    ln_kernel<<<MM, 128>>>(inputs, ln1_scale, ln1_offset, x1);

    // 2. fused QKV projections
    mma_qkv_kernel<<<dim3(DD/128, MM/128, 3), 256>>>(x1, wtq, bq, q, wtk, bk, k, wtv, bv, v);

    // 3. flash attention
    attn_kernel<<<dim3(TT/128, BB*HH), 256, 98304>>>(q, k, v, ctx);

    // 4. output projection + residual
    mma_gemm_kernel<2><<<dim3(DD/128, MM/128), 256>>>(ctx, wto, bo, inputs, x, DD, DD);

    // 5. LN2
    ln_kernel<<<MM, 128>>>(x, ln2_scale, ln2_offset, y);

    // 6. FFN up + GELU
    mma_gemm_kernel<1><<<dim3(FF/128, MM/128), 256>>>(y, wt1, b1, nullptr, hbuf, FF, DD);

    // 7. FFN down + residual -> out
    mma_gemm_kernel<2><<<dim3(DD/128, MM/128), 256>>>(hbuf, wt2, b2, x, out, DD, FF);
}

// round 5
// speedup vs baseline: 5.9555x; 1.7814x over previous
#include <cuda_runtime.h>
#include <cuda_bf16.h>
#include <math.h>
#include <stdint.h>

#define BB 2
#define TT 4096
#define DD 512
#define HH 8
#define HK 64
#define FF 2048
#define MM (BB*TT)   // 8192 rows

// ---------------- scratch (no allocs allowed) ----------------
__device__ float g_x1 [MM*DD];
__device__ float g_q  [MM*DD];
__device__ float g_k  [MM*DD];
__device__ float g_v  [MM*DD];
__device__ float g_ctx[MM*DD];
__device__ float g_x  [MM*DD];
__device__ float g_y  [MM*DD];
__device__ float g_h  [MM*FF];
// transposed weights [N][K]
__device__ float g_wtq[DD*DD];
__device__ float g_wtk[DD*DD];
__device__ float g_wtv[DD*DD];
__device__ float g_wto[DD*DD];
__device__ float g_wt1[FF*DD];
__device__ float g_wt2[DD*FF];

// ================= helpers (sm_80-era only: compute_103-safe) =================
__device__ __forceinline__ uint32_t smem_u32(const void* p) {
    uint32_t a;
    asm("{ .reg .u64 t; cvta.to.shared.u64 t, %1; cvt.u32.u64 %0, t; }" : "=r"(a) : "l"(p));
    return a;
}
__device__ __forceinline__ void ldm4(uint32_t* r, uint32_t addr) {
    asm volatile("ldmatrix.sync.aligned.m8n8.x4.shared.b16 {%0,%1,%2,%3}, [%4];"
        : "=r"(r[0]), "=r"(r[1]), "=r"(r[2]), "=r"(r[3]) : "r"(addr));
}
__device__ __forceinline__ void ldm4t(uint32_t* r, uint32_t addr) {
    asm volatile("ldmatrix.sync.aligned.m8n8.x4.trans.shared.b16 {%0,%1,%2,%3}, [%4];"
        : "=r"(r[0]), "=r"(r[1]), "=r"(r[2]), "=r"(r[3]) : "r"(addr));
}
__device__ __forceinline__ void mma_bf16(float* c, const uint32_t* a, uint32_t b0, uint32_t b1) {
    asm volatile("mma.sync.aligned.m16n8k16.row.col.f32.bf16.bf16.f32 "
        "{%0,%1,%2,%3}, {%4,%5,%6,%7}, {%8,%9}, {%0,%1,%2,%3};"
        : "+f"(c[0]), "+f"(c[1]), "+f"(c[2]), "+f"(c[3])
        : "r"(a[0]), "r"(a[1]), "r"(a[2]), "r"(a[3]), "r"(b0), "r"(b1));
}
__device__ __forceinline__ float ex2f(float x) {
    float r;
    asm("ex2.approx.f32 %0, %1;" : "=f"(r) : "f"(x));
    return r;
}
#define STS64U(addr, r0, r1) \
    asm volatile("st.shared.v2.b32 [%0], {%1,%2};" :: "r"(addr), "r"(r0), "r"(r1) : "memory")

// split fp32 pair -> packed bf16 hi and lo words
__device__ __forceinline__ void split2(float x0, float x1, uint32_t& hi, uint32_t& lo) {
    __nv_bfloat16 h0 = __float2bfloat16_rn(x0);
    __nv_bfloat16 h1 = __float2bfloat16_rn(x1);
    __nv_bfloat16 l0 = __float2bfloat16_rn(x0 - __bfloat162float(h0));
    __nv_bfloat16 l1 = __float2bfloat16_rn(x1 - __bfloat162float(h1));
    hi = (uint32_t)__bfloat16_as_ushort(h0) | ((uint32_t)__bfloat16_as_ushort(h1) << 16);
    lo = (uint32_t)__bfloat16_as_ushort(l0) | ((uint32_t)__bfloat16_as_ushort(l1) << 16);
}

// ---------------- LayerNorm ----------------
__global__ void __launch_bounds__(128) ln_kernel(const float* __restrict__ x,
                                                 const float* __restrict__ sc,
                                                 const float* __restrict__ of,
                                                 float* __restrict__ out) {
    int row = blockIdx.x;
    int tid = threadIdx.x;
    const float4* xr = (const float4*)(x + (size_t)row * DD);
    float4 v = xr[tid];
    float s  = v.x + v.y + v.z + v.w;
    float ss = v.x*v.x + v.y*v.y + v.z*v.z + v.w*v.w;
    #pragma unroll
    for (int o = 16; o > 0; o >>= 1) {
        s  += __shfl_xor_sync(0xffffffffu, s,  o);
        ss += __shfl_xor_sync(0xffffffffu, ss, o);
    }
    __shared__ float s_s[4], s_ss[4];
    int wid = tid >> 5, lane = tid & 31;
    if (lane == 0) { s_s[wid] = s; s_ss[wid] = ss; }
    __syncthreads();
    s  = s_s[0]  + s_s[1]  + s_s[2]  + s_s[3];
    ss = s_ss[0] + s_ss[1] + s_ss[2] + s_ss[3];
    float mean = s * (1.0f / DD);
    float var  = ss * (1.0f / DD) - mean * mean;
    float inv  = rsqrtf(var + 1e-5f);
    float4 scv = ((const float4*)sc)[tid];
    float4 ofv = ((const float4*)of)[tid];
    float4 o;
    o.x = (v.x - mean) * inv * scv.x + ofv.x;
    o.y = (v.y - mean) * inv * scv.y + ofv.y;
    o.z = (v.z - mean) * inv * scv.z + ofv.z;
    o.w = (v.w - mean) * inv * scv.w + ofv.w;
    ((float4*)(out + (size_t)row * DD))[tid] = o;
}

// ---------------- weight transpose ----------------
__global__ void __launch_bounds__(256) transpose_kernel(const float* __restrict__ S,
                                                        float* __restrict__ D, int R, int C) {
    __shared__ float t[32][33];
    int bx = blockIdx.x * 32, by = blockIdx.y * 32;
    int x = threadIdx.x & 31, y = (threadIdx.x >> 5) * 4;
    #pragma unroll
    for (int i = 0; i < 4; i++)
        t[y + i][x] = S[(size_t)(by + y + i) * C + bx + x];
    __syncthreads();
    #pragma unroll
    for (int i = 0; i < 4; i++)
        D[(size_t)(bx + y + i) * R + by + x] = t[x][y + i];
}

// ---------------- bf16x3 mma.sync GEMM (unchanged from R4) ----------------
__device__ __forceinline__ float gelu_tanh(float x) {
    float x3 = x * x * x;
    return 0.5f * x * (1.0f + tanhf(0.7978845608028654f * (x + 0.044715f * x3)));
}

#define RS 40

template <int EPI>
__device__ __forceinline__ void mma_gemm_core(const float* __restrict__ A,
                                              const float* __restrict__ Bt,
                                              const float* __restrict__ bias,
                                              const float* __restrict__ res,
                                              float* __restrict__ C,
                                              int N, int Kd) {
    __shared__ __align__(16) __nv_bfloat16 sAh[128 * RS];
    __shared__ __align__(16) __nv_bfloat16 sAl[128 * RS];
    __shared__ __align__(16) __nv_bfloat16 sBh[128 * RS];
    __shared__ __align__(16) __nv_bfloat16 sBl[128 * RS];
    const uint32_t aAh = smem_u32(sAh), aAl = smem_u32(sAl);
    const uint32_t aBh = smem_u32(sBh), aBl = smem_u32(sBl);

    const int tid  = threadIdx.x;
    const int lane = tid & 31, warp = tid >> 5;
    const int wm = warp >> 1, wn = warp & 1;
    const int m0 = blockIdx.y * 128;
    const int n0 = blockIdx.x * 128;

    const int g = lane >> 3, lr = lane & 7;
    uint32_t offA[2][2], offB[4][2];
    #pragma unroll
    for (int t = 0; t < 2; t++) {
        int row = wm * 32 + t * 16 + (g & 1) * 8 + lr;
        #pragma unroll
        for (int ks = 0; ks < 2; ks++)
            offA[t][ks] = (uint32_t)(row * (RS * 2) + (ks * 16 + (g >> 1) * 8) * 2);
    }
    #pragma unroll
    for (int p = 0; p < 4; p++) {
        int row = wn * 64 + p * 16 + (g >> 1) * 8 + lr;
        #pragma unroll
        for (int ks = 0; ks < 2; ks++)
            offB[p][ks] = (uint32_t)(row * (RS * 2) + (ks * 16 + (g & 1) * 8) * 2);
    }

    const int rr = tid >> 3;
    const int c4 = (tid & 7) * 4;
    const uint32_t sOff = (uint32_t)(rr * (RS * 2) + c4 * 2);

    float acc[2][8][4];
    #pragma unroll
    for (int mt = 0; mt < 2; mt++)
        #pragma unroll
        for (int nt = 0; nt < 8; nt++)
            #pragma unroll
            for (int j = 0; j < 4; j++) acc[mt][nt][j] = 0.0f;

    float4 av[4], bv[4];
    #pragma unroll
    for (int i = 0; i < 4; i++) {
        av[i] = *(const float4*)(A  + (size_t)(m0 + rr + i * 32) * Kd + c4);
        bv[i] = *(const float4*)(Bt + (size_t)(n0 + rr + i * 32) * Kd + c4);
    }

    const int nchunk = Kd >> 5;
    for (int ck = 0; ck < nchunk; ck++) {
        __syncthreads();
        #pragma unroll
        for (int i = 0; i < 4; i++) {
            uint32_t so = sOff + (uint32_t)(i * 32 * RS * 2);
            uint32_t h0, l0, h1, l1;
            split2(av[i].x, av[i].y, h0, l0);
            split2(av[i].z, av[i].w, h1, l1);
            STS64U(aAh + so, h0, h1);
            STS64U(aAl + so, l0, l1);
            split2(bv[i].x, bv[i].y, h0, l0);
            split2(bv[i].z, bv[i].w, h1, l1);
            STS64U(aBh + so, h0, h1);
            STS64U(aBl + so, l0, l1);
        }
        __syncthreads();
        if (ck + 1 < nchunk) {
            const int k0 = (ck + 1) * 32;
            #pragma unroll
            for (int i = 0; i < 4; i++) {
                av[i] = *(const float4*)(A  + (size_t)(m0 + rr + i * 32) * Kd + k0 + c4);
                bv[i] = *(const float4*)(Bt + (size_t)(n0 + rr + i * 32) * Kd + k0 + c4);
            }
        }
        #pragma unroll
        for (int ks = 0; ks < 2; ks++) {
            uint32_t ah[2][4], al[2][4];
            ldm4(ah[0], aAh + offA[0][ks]);
            ldm4(ah[1], aAh + offA[1][ks]);
            ldm4(al[0], aAl + offA[0][ks]);
            ldm4(al[1], aAl + offA[1][ks]);
            uint32_t bh[4][4], bl[4][4];
            #pragma unroll
            for (int p = 0; p < 4; p++) {
                ldm4(bh[p], aBh + offB[p][ks]);
                ldm4(bl[p], aBl + offB[p][ks]);
            }
            #pragma unroll
            for (int mt = 0; mt < 2; mt++)
                #pragma unroll
                for (int nt = 0; nt < 8; nt++) {
                    uint32_t bh0 = bh[nt >> 1][(nt & 1) * 2], bh1 = bh[nt >> 1][(nt & 1) * 2 + 1];
                    uint32_t bl0 = bl[nt >> 1][(nt & 1) * 2], bl1 = bl[nt >> 1][(nt & 1) * 2 + 1];
                    mma_bf16(acc[mt][nt], ah[mt], bh0, bh1);
                    mma_bf16(acc[mt][nt], ah[mt], bl0, bl1);
                    mma_bf16(acc[mt][nt], al[mt], bh0, bh1);
                }
        }
    }

    const int erow = m0 + wm * 32 + (lane >> 2);
    const int ecol = n0 + wn * 64 + (lane & 3) * 2;
    #pragma unroll
    for (int mt = 0; mt < 2; mt++) {
        #pragma unroll
        for (int nt = 0; nt < 8; nt++) {
            const int col = ecol + nt * 8;
            float2 bz = *(const float2*)&bias[col];
            float v0 = acc[mt][nt][0] + bz.x;
            float v1 = acc[mt][nt][1] + bz.y;
            float v2 = acc[mt][nt][2] + bz.x;
            float v3 = acc[mt][nt][3] + bz.y;
            int r0 = erow + mt * 16, r1 = r0 + 8;
            if (EPI == 1) {
                v0 = gelu_tanh(v0); v1 = gelu_tanh(v1);
                v2 = gelu_tanh(v2); v3 = gelu_tanh(v3);
            }
            if (EPI == 2) {
                float2 ra = *(const float2*)&res[(size_t)r0 * N + col];
                float2 rb = *(const float2*)&res[(size_t)r1 * N + col];
                v0 += ra.x; v1 += ra.y; v2 += rb.x; v3 += rb.y;
            }
            float2 w0 = {v0, v1}, w1 = {v2, v3};
            *(float2*)&C[(size_t)r0 * N + col] = w0;
            *(float2*)&C[(size_t)r1 * N + col] = w1;
        }
    }
}

template <int EPI>
__global__ void __launch_bounds__(256, 1) mma_gemm_kernel(const float* __restrict__ A,
                                                          const float* __restrict__ Bt,
                                                          const float* __restrict__ bias,
                                                          const float* __restrict__ res,
                                                          float* __restrict__ C,
                                                          int N, int Kd) {
    mma_gemm_core<EPI>(A, Bt, bias, res, C, N, Kd);
}

__global__ void __launch_bounds__(256, 1) mma_qkv_kernel(const float* __restrict__ A,
        const float* __restrict__ wtq, const float* __restrict__ bq, float* __restrict__ q,
        const float* __restrict__ wtk, const float* __restrict__ bk, float* __restrict__ k,
        const float* __restrict__ wtv, const float* __restrict__ bv, float* __restrict__ v) {
    const float* W; const float* bz; float* O;
    if (blockIdx.z == 0)      { W = wtq; bz = bq; O = q; }
    else if (blockIdx.z == 1) { W = wtk; bz = bk; O = k; }
    else                      { W = wtv; bz = bv; O = v; }
    mma_gemm_core<0>(A, W, bz, nullptr, O, DD, DD);
}

// ---------------- Flash attention on mma.sync (bf16 hi/lo x3) ----------------
// CTA: 128 q rows of one (b,h); 8 warps x 16 q. Key tiles of 64.
// smem: Qh/Ql [128][72bf16], Kh/Kl [64][72], Vh/Vl [64][72]  (stride 144B, conflict-free)
#define ASR 72
#define ASRB 144
#define Q_SZ  (128 * ASR * 2)     // 18432 B
#define KV_SZ (64 * ASR * 2)      //  9216 B
#define ATT_SMEM (2*Q_SZ + 4*KV_SZ)  // 73728 B

__global__ void __launch_bounds__(256) attn_mma_kernel(const float* __restrict__ Q,
                                                       const float* __restrict__ Kg,
                                                       const float* __restrict__ Vg,
                                                       float* __restrict__ Og) {
    extern __shared__ __align__(16) char asmem[];
    const uint32_t aQh = smem_u32(asmem);
    const uint32_t aQl = aQh + Q_SZ;
    const uint32_t aKh = aQl + Q_SZ;
    const uint32_t aKl = aKh + KV_SZ;
    const uint32_t aVh = aKl + KV_SZ;
    const uint32_t aVl = aVh + KV_SZ;

    const int tid  = threadIdx.x;
    const int lane = tid & 31, warp = tid >> 5;
    const int b = blockIdx.y >> 3, h = blockIdx.y & 7;
    const int qt = blockIdx.x * 128;

    const float* Qb = Q  + ((size_t)b * TT) * DD + h * HK;
    const float* Kb = Kg + ((size_t)b * TT) * DD + h * HK;
    const float* Vb = Vg + ((size_t)b * TT) * DD + h * HK;

    // ---- load Q tile: scale by 0.125*log2(e), split to bf16 hi/lo ----
    const float QSC = 0.125f * 1.4426950408889634f;
    #pragma unroll
    for (int i = 0; i < 8; i++) {
        int idx = tid + i * 256;
        int row = idx >> 4, c4 = (idx & 15) * 4;
        float4 qv = *(const float4*)(Qb + (size_t)(qt + row) * DD + c4);
        qv.x *= QSC; qv.y *= QSC; qv.z *= QSC; qv.w *= QSC;
        uint32_t h0, l0, h1, l1;
        split2(qv.x, qv.y, h0, l0);
        split2(qv.z, qv.w, h1, l1);
        uint32_t so = (uint32_t)(row * ASRB + c4 * 2);
        STS64U(aQh + so, h0, h1);
        STS64U(aQl + so, l0, l1);
    }

    // ldmatrix lane offsets
    const int g = lane >> 3, lr = lane & 7;
    const uint32_t qoff = (uint32_t)((warp * 16 + (g & 1) * 8 + lr) * ASRB + (g >> 1) * 16);
    const uint32_t koff = (uint32_t)(((g >> 1) * 8 + lr) * ASRB + (g & 1) * 16);
    const uint32_t voff = (uint32_t)(((g & 1) * 8 + lr) * ASRB + (g >> 1) * 16);

    // K/V gmem prefetch mapping
    const int rr0 = tid >> 4;            // 0..15 (rows advance by 16 per i)
    const int c40 = (tid & 15) * 4;
    const uint32_t kvso = (uint32_t)(rr0 * ASRB + c40 * 2);

    float4 kpf[4], vpf[4];
    #pragma unroll
    for (int i = 0; i < 4; i++) {
        kpf[i] = *(const float4*)(Kb + (size_t)(rr0 + i * 16) * DD + c40);
        vpf[i] = *(const float4*)(Vb + (size_t)(rr0 + i * 16) * DD + c40);
    }

    float m0 = -1e30f, m1 = -1e30f, l0 = 0.0f, l1 = 0.0f;
    float oacc[8][4];
    #pragma unroll
    for (int nt = 0; nt < 8; nt++)
        #pragma unroll
        for (int j = 0; j < 4; j++) oacc[nt][j] = 0.0f;

    const int NTILE = TT / 64;
    for (int kt = 0; kt < NTILE; kt++) {
        __syncthreads();   // previous compute done reading K/V smem (covers Q STS at kt=0)
        #pragma unroll
        for (int i = 0; i < 4; i++) {
            uint32_t so = kvso + (uint32_t)(i * 16 * ASRB);
            uint32_t h0, l0w, h1, l1w;
            split2(kpf[i].x, kpf[i].y, h0, l0w);
            split2(kpf[i].z, kpf[i].w, h1, l1w);
            STS64U(aKh + so, h0, h1);
            STS64U(aKl + so, l0w, l1w);
            split2(vpf[i].x, vpf[i].y, h0, l0w);
            split2(vpf[i].z, vpf[i].w, h1, l1w);
            STS64U(aVh + so, h0, h1);
            STS64U(aVl + so, l0w, l1w);
        }
        __syncthreads();
        if (kt + 1 < NTILE) {
            const size_t kb = (size_t)(kt + 1) * 64;
            #pragma unroll
            for (int i = 0; i < 4; i++) {
                kpf[i] = *(const float4*)(Kb + (kb + rr0 + i * 16) * DD + c40);
                vpf[i] = *(const float4*)(Vb + (kb + rr0 + i * 16) * DD + c40);
            }
        }

        // ---- S = Q K^T (16q x 64keys per warp) ----
        float sacc[8][4];
        #pragma unroll
        for (int nt = 0; nt < 8; nt++)
            #pragma unroll
            for (int j = 0; j < 4; j++) sacc[nt][j] = 0.0f;

        #pragma unroll
        for (int ks = 0; ks < 4; ks++) {
            uint32_t qah[4], qal[4];
            ldm4(qah, aQh + qoff + ks * 32);
            ldm4(qal, aQl + qoff + ks * 32);
            uint32_t kbh[4][4], kbl[4][4];
            #pragma unroll
            for (int p = 0; p < 4; p++) {
                ldm4(kbh[p], aKh + koff + (uint32_t)(p * 16 * ASRB) + ks * 32);
                ldm4(kbl[p], aKl + koff + (uint32_t)(p * 16 * ASRB) + ks * 32);
            }
            #pragma unroll
            for (int nt = 0; nt < 8; nt++) {
                uint32_t b0h = kbh[nt >> 1][(nt & 1) * 2], b1h = kbh[nt >> 1][(nt & 1) * 2 + 1];
                uint32_t b0l = kbl[nt >> 1][(nt & 1) * 2], b1l = kbl[nt >> 1][(nt & 1) * 2 + 1];
                mma_bf16(sacc[nt], qah, b0h, b1h);
                mma_bf16(sacc[nt], qah, b0l, b1l);
                mma_bf16(sacc[nt], qal, b0h, b1h);
            }
        }

        // ---- online softmax (rows r=lane>>2 and r+8; logits already in log2 domain) ----
        float mx0 = -1e30f, mx1 = -1e30f;
        #pragma unroll
        for (int nt = 0; nt < 8; nt++) {
            mx0 = fmaxf(mx0, fmaxf(sacc[nt][0], sacc[nt][1]));
            mx1 = fmaxf(mx1, fmaxf(sacc[nt][2], sacc[nt][3]));
        }
        mx0 = fmaxf(mx0, __shfl_xor_sync(0xffffffffu, mx0, 1));
        mx0 = fmaxf(mx0, __shfl_xor_sync(0xffffffffu, mx0, 2));
        mx1 = fmaxf(mx1, __shfl_xor_sync(0xffffffffu, mx1, 1));
        mx1 = fmaxf(mx1, __shfl_xor_sync(0xffffffffu, mx1, 2));
        float nm0 = fmaxf(m0, mx0), nm1 = fmaxf(m1, mx1);
        float al0 = ex2f(m0 - nm0), al1 = ex2f(m1 - nm1);
        m0 = nm0; m1 = nm1;
        #pragma unroll
        for (int nt = 0; nt < 8; nt++) {
            oacc[nt][0] *= al0; oacc[nt][1] *= al0;
            oacc[nt][2] *= al1; oacc[nt][3] *= al1;
        }
        float rs0 = 0.0f, rs1 = 0.0f;

        // ---- O += P V (P built in registers from sacc) ----
        #pragma unroll
        for (int kp = 0; kp < 4; kp++) {
            uint32_t pah[4], pal[4];
            #pragma unroll
            for (int j = 0; j < 2; j++) {
                int nt = 2 * kp + j;
                float p00 = ex2f(sacc[nt][0] - nm0);
                float p01 = ex2f(sacc[nt][1] - nm0);
                float p10 = ex2f(sacc[nt][2] - nm1);
                float p11 = ex2f(sacc[nt][3] - nm1);
                rs0 += p00 + p01; rs1 += p10 + p11;
                split2(p00, p01, pah[2 * j],     pal[2 * j]);
                split2(p10, p11, pah[2 * j + 1], pal[2 * j + 1]);
            }
            uint32_t vbh[4][4], vbl[4][4];
            #pragma unroll
            for (int gv = 0; gv < 4; gv++) {
                ldm4t(vbh[gv], aVh + voff + (uint32_t)(kp * 16 * ASRB) + gv * 32);
                ldm4t(vbl[gv], aVl + voff + (uint32_t)(kp * 16 * ASRB) + gv * 32);
            }
            #pragma unroll
            for (int nt = 0; nt < 8; nt++) {
                uint32_t b0h = vbh[nt >> 1][(nt & 1) * 2], b1h = vbh[nt >> 1][(nt & 1) * 2 + 1];
                uint32_t b0l = vbl[nt >> 1][(nt & 1) * 2], b1l = vbl[nt >> 1][(nt & 1) * 2 + 1];
                mma_bf16(oacc[nt], pah, b0h, b1h);
                mma_bf16(oacc[nt], pah, b0l, b1l);
                mma_bf16(oacc[nt], pal, b0h, b1h);
            }
        }
        rs0 += __shfl_xor_sync(0xffffffffu, rs0, 1);
        rs0 += __shfl_xor_sync(0xffffffffu, rs0, 2);
        rs1 += __shfl_xor_sync(0xffffffffu, rs1, 1);
        rs1 += __shfl_xor_sync(0xffffffffu, rs1, 2);
        l0 = l0 * al0 + rs0;
        l1 = l1 * al1 + rs1;
    }

    // ---- write ctx ----
    const float inv0 = 1.0f / l0, inv1 = 1.0f / l1;
    const int qr0 = qt + warp * 16 + (lane >> 2);
    const int colb = h * HK + (lane & 3) * 2;
    #pragma unroll
    for (int nt = 0; nt < 8; nt++) {
        float2 w0 = {oacc[nt][0] * inv0, oacc[nt][1] * inv0};
        float2 w1 = {oacc[nt][2] * inv1, oacc[nt][3] * inv1};
        *(float2*)(Og + ((size_t)b * TT + qr0)     * DD + colb + nt * 8) = w0;
        *(float2*)(Og + ((size_t)b * TT + qr0 + 8) * DD + colb + nt * 8) = w1;
    }
}

// ---------------- launch ----------------
extern "C" void kernel_launch(void* const* d_in, const int* in_sizes, int n_in,
                              void* d_out, int out_size) {
    const float* inputs     = (const float*)d_in[0];
    const float* ln1_scale  = (const float*)d_in[1];
    const float* ln1_offset = (const float*)d_in[2];
    const float* wq = (const float*)d_in[3];
    const float* bq = (const float*)d_in[4];
    const float* wk = (const float*)d_in[5];
    const float* bk = (const float*)d_in[6];
    const float* wv = (const float*)d_in[7];
    const float* bv = (const float*)d_in[8];
    const float* wo = (const float*)d_in[9];
    const float* bo = (const float*)d_in[10];
    const float* ln2_scale  = (const float*)d_in[11];
    const float* ln2_offset = (const float*)d_in[12];
    const float* w1 = (const float*)d_in[13];
    const float* b1 = (const float*)d_in[14];
    const float* w2 = (const float*)d_in[15];
    const float* b2 = (const float*)d_in[16];
    float* out = (float*)d_out;

    float *x1, *q, *k, *v, *ctx, *x, *y, *hbuf;
    float *wtq, *wtk, *wtv, *wto, *wt1, *wt2;
    cudaGetSymbolAddress((void**)&x1,   g_x1);
    cudaGetSymbolAddress((void**)&q,    g_q);
    cudaGetSymbolAddress((void**)&k,    g_k);
    cudaGetSymbolAddress((void**)&v,    g_v);
    cudaGetSymbolAddress((void**)&ctx,  g_ctx);
    cudaGetSymbolAddress((void**)&x,    g_x);
    cudaGetSymbolAddress((void**)&y,    g_y);
    cudaGetSymbolAddress((void**)&hbuf, g_h);
    cudaGetSymbolAddress((void**)&wtq,  g_wtq);
    cudaGetSymbolAddress((void**)&wtk,  g_wtk);
    cudaGetSymbolAddress((void**)&wtv,  g_wtv);
    cudaGetSymbolAddress((void**)&wto,  g_wto);
    cudaGetSymbolAddress((void**)&wt1,  g_wt1);
    cudaGetSymbolAddress((void**)&wt2,  g_wt2);

    cudaFuncSetAttribute(attn_mma_kernel, cudaFuncAttributeMaxDynamicSharedMemorySize, ATT_SMEM);

    // 0. weight transposes ([K,N] -> [N,K])
    transpose_kernel<<<dim3(DD/32, DD/32), 256>>>(wq, wtq, DD, DD);
    transpose_kernel<<<dim3(DD/32, DD/32), 256>>>(wk, wtk, DD, DD);
    transpose_kernel<<<dim3(DD/32, DD/32), 256>>>(wv, wtv, DD, DD);
    transpose_kernel<<<dim3(DD/32, DD/32), 256>>>(wo, wto, DD, DD);
    transpose_kernel<<<dim3(FF/32, DD/32), 256>>>(w1, wt1, DD, FF);
    transpose_kernel<<<dim3(DD/32, FF/32), 256>>>(w2, wt2, FF, DD);

    // 1. LN1
    ln_kernel<<<MM, 128>>>(inputs, ln1_scale, ln1_offset, x1);

    // 2. fused QKV projections
    mma_qkv_kernel<<<dim3(DD/128, MM/128, 3), 256>>>(x1, wtq, bq, q, wtk, bk, k, wtv, bv, v);

    // 3. flash attention (tensor core)
    attn_mma_kernel<<<dim3(TT/128, BB*HH), 256, ATT_SMEM>>>(q, k, v, ctx);

    // 4. output projection + residual
    mma_gemm_kernel<2><<<dim3(DD/128, MM/128), 256>>>(ctx, wto, bo, inputs, x, DD, DD);

    // 5. LN2
    ln_kernel<<<MM, 128>>>(x, ln2_scale, ln2_offset, y);

    // 6. FFN up + GELU
    mma_gemm_kernel<1><<<dim3(FF/128, MM/128), 256>>>(y, wt1, b1, nullptr, hbuf, FF, DD);

    // 7. FFN down + residual -> out
    mma_gemm_kernel<2><<<dim3(DD/128, MM/128), 256>>>(hbuf, wt2, b2, x, out, DD, FF);
}

// round 6
// speedup vs baseline: 7.5950x; 1.2753x over previous
#include <cuda_runtime.h>
#include <cuda_bf16.h>
#include <math.h>
#include <stdint.h>

#define BB 2
#define TT 4096
#define DD 512
#define HH 8
#define HK 64
#define FF 2048
#define MM (BB*TT)   // 8192 rows

// ---------------- scratch (no allocs allowed) ----------------
__device__ __nv_bfloat16 g_x1h[MM*DD], g_x1l[MM*DD];
__device__ __nv_bfloat16 g_qh [MM*DD], g_ql [MM*DD];
__device__ __nv_bfloat16 g_kh [MM*DD], g_kl [MM*DD];
__device__ __nv_bfloat16 g_vh [MM*DD], g_vl [MM*DD];
__device__ __nv_bfloat16 g_ctxh[MM*DD], g_ctxl[MM*DD];
__device__ float         g_x  [MM*DD];
__device__ __nv_bfloat16 g_yh [MM*DD], g_yl [MM*DD];
__device__ __nv_bfloat16 g_hh [MM*FF], g_hl [MM*FF];
__device__ __nv_bfloat16 g_wtqh[DD*DD], g_wtql[DD*DD];
__device__ __nv_bfloat16 g_wtkh[DD*DD], g_wtkl[DD*DD];
__device__ __nv_bfloat16 g_wtvh[DD*DD], g_wtvl[DD*DD];
__device__ __nv_bfloat16 g_wtoh[DD*DD], g_wtol[DD*DD];
__device__ __nv_bfloat16 g_wt1h[FF*DD], g_wt1l[FF*DD];
__device__ __nv_bfloat16 g_wt2h[DD*FF], g_wt2l[DD*FF];

// ================= helpers (sm_80-era only: compute_103-safe) =================
__device__ __forceinline__ uint32_t smem_u32(const void* p) {
    uint32_t a;
    asm("{ .reg .u64 t; cvta.to.shared.u64 t, %1; cvt.u32.u64 %0, t; }" : "=r"(a) : "l"(p));
    return a;
}
__device__ __forceinline__ void ldm4(uint32_t* r, uint32_t addr) {
    asm volatile("ldmatrix.sync.aligned.m8n8.x4.shared.b16 {%0,%1,%2,%3}, [%4];"
        : "=r"(r[0]), "=r"(r[1]), "=r"(r[2]), "=r"(r[3]) : "r"(addr));
}
__device__ __forceinline__ void ldm4t(uint32_t* r, uint32_t addr) {
    asm volatile("ldmatrix.sync.aligned.m8n8.x4.trans.shared.b16 {%0,%1,%2,%3}, [%4];"
        : "=r"(r[0]), "=r"(r[1]), "=r"(r[2]), "=r"(r[3]) : "r"(addr));
}
__device__ __forceinline__ void mma_bf16(float* c, const uint32_t* a, uint32_t b0, uint32_t b1) {
    asm volatile("mma.sync.aligned.m16n8k16.row.col.f32.bf16.bf16.f32 "
        "{%0,%1,%2,%3}, {%4,%5,%6,%7}, {%8,%9}, {%0,%1,%2,%3};"
        : "+f"(c[0]), "+f"(c[1]), "+f"(c[2]), "+f"(c[3])
        : "r"(a[0]), "r"(a[1]), "r"(a[2]), "r"(a[3]), "r"(b0), "r"(b1));
}
__device__ __forceinline__ float ex2f(float x) {
    float r;
    asm("ex2.approx.f32 %0, %1;" : "=f"(r) : "f"(x));
    return r;
}
__device__ __forceinline__ void cpa16(uint32_t dst, const void* src) {
    asm volatile("cp.async.cg.shared.global [%0], [%1], 16;" :: "r"(dst), "l"(src));
}
#define CP_COMMIT() asm volatile("cp.async.commit_group;" ::: "memory")
#define CP_WAIT1()  asm volatile("cp.async.wait_group 1;"  ::: "memory")
#define CP_WAIT0()  asm volatile("cp.async.wait_group 0;"  ::: "memory")
#define STS128Q(addr, v) \
    asm volatile("st.shared.v4.b32 [%0], {%1,%2,%3,%4};" \
        :: "r"(addr), "r"((v).x), "r"((v).y), "r"((v).z), "r"((v).w) : "memory")

// split fp32 pair -> packed bf16 hi and lo words
__device__ __forceinline__ void split2(float x0, float x1, uint32_t& hi, uint32_t& lo) {
    __nv_bfloat16 h0 = __float2bfloat16_rn(x0);
    __nv_bfloat16 h1 = __float2bfloat16_rn(x1);
    __nv_bfloat16 l0 = __float2bfloat16_rn(x0 - __bfloat162float(h0));
    __nv_bfloat16 l1 = __float2bfloat16_rn(x1 - __bfloat162float(h1));
    hi = (uint32_t)__bfloat16_as_ushort(h0) | ((uint32_t)__bfloat16_as_ushort(h1) << 16);
    lo = (uint32_t)__bfloat16_as_ushort(l0) | ((uint32_t)__bfloat16_as_ushort(l1) << 16);
}

// ---------------- LayerNorm: fp32 in -> bf16 hi/lo out ----------------
__global__ void __launch_bounds__(128) ln_kernel(const float* __restrict__ x,
                                                 const float* __restrict__ sc,
                                                 const float* __restrict__ of,
                                                 __nv_bfloat16* __restrict__ outh,
                                                 __nv_bfloat16* __restrict__ outl) {
    int row = blockIdx.x;
    int tid = threadIdx.x;
    const float4* xr = (const float4*)(x + (size_t)row * DD);
    float4 v = xr[tid];
    float s  = v.x + v.y + v.z + v.w;
    float ss = v.x*v.x + v.y*v.y + v.z*v.z + v.w*v.w;
    #pragma unroll
    for (int o = 16; o > 0; o >>= 1) {
        s  += __shfl_xor_sync(0xffffffffu, s,  o);
        ss += __shfl_xor_sync(0xffffffffu, ss, o);
    }
    __shared__ float s_s[4], s_ss[4];
    int wid = tid >> 5, lane = tid & 31;
    if (lane == 0) { s_s[wid] = s; s_ss[wid] = ss; }
    __syncthreads();
    s  = s_s[0]  + s_s[1]  + s_s[2]  + s_s[3];
    ss = s_ss[0] + s_ss[1] + s_ss[2] + s_ss[3];
    float mean = s * (1.0f / DD);
    float var  = ss * (1.0f / DD) - mean * mean;
    float inv  = rsqrtf(var + 1e-5f);
    float4 scv = ((const float4*)sc)[tid];
    float4 ofv = ((const float4*)of)[tid];
    float o0 = (v.x - mean) * inv * scv.x + ofv.x;
    float o1 = (v.y - mean) * inv * scv.y + ofv.y;
    float o2 = (v.z - mean) * inv * scv.z + ofv.z;
    float o3 = (v.w - mean) * inv * scv.w + ofv.w;
    uint32_t h0, l0, h1, l1;
    split2(o0, o1, h0, l0);
    split2(o2, o3, h1, l1);
    uint2 wh = {h0, h1}, wl = {l0, l1};
    *(uint2*)(outh + (size_t)row * DD + tid * 4) = wh;
    *(uint2*)(outl + (size_t)row * DD + tid * 4) = wl;
}

// ---------------- fused weight transpose + split: fp32 [R][C] -> bf16 hi/lo [C][R] ----------------
__global__ void __launch_bounds__(256) tsplit_kernel(const float* __restrict__ S,
                                                     __nv_bfloat16* __restrict__ Dh,
                                                     __nv_bfloat16* __restrict__ Dl,
                                                     int R, int C) {
    __shared__ float t[32][33];
    int bx = blockIdx.x * 32, by = blockIdx.y * 32;
    int x = threadIdx.x & 31, y = (threadIdx.x >> 5) * 4;
    #pragma unroll
    for (int i = 0; i < 4; i++)
        t[y + i][x] = S[(size_t)(by + y + i) * C + bx + x];
    __syncthreads();
    #pragma unroll
    for (int i = 0; i < 4; i++) {
        float val = t[x][y + i];
        __nv_bfloat16 hb = __float2bfloat16_rn(val);
        __nv_bfloat16 lb = __float2bfloat16_rn(val - __bfloat162float(hb));
        size_t idx = (size_t)(bx + y + i) * R + by + x;
        Dh[idx] = hb;
        Dl[idx] = lb;
    }
}

// ---------------- bf16x3 mma.sync GEMM, cp.async double-buffered ----------------
__device__ __forceinline__ float gelu_tanh(float x) {
    float x3 = x * x * x;
    return 0.5f * x * (1.0f + tanhf(0.7978845608028654f * (x + 0.044715f * x3)));
}

#define RS 40
#define GARR 10240          // one array: 128 rows * 40 bf16 * 2B
#define GBUF (4*GARR)       // 40960 per stage
#define GEMM_SMEM (2*GBUF)  // 81920

// EPI: 0 = bias (+oscale) -> bf16 hi/lo out; 1 = bias+gelu -> bf16 hi/lo; 2 = bias+residual -> fp32
template <int EPI>
__device__ __forceinline__ void gemm2_core(
    const __nv_bfloat16* __restrict__ Ah, const __nv_bfloat16* __restrict__ Al,
    const __nv_bfloat16* __restrict__ Bh, const __nv_bfloat16* __restrict__ Bl,
    const float* __restrict__ bias, const float* __restrict__ res,
    float* __restrict__ Cf, __nv_bfloat16* __restrict__ Ch, __nv_bfloat16* __restrict__ Cl,
    int N, int Kd, float oscale)
{
    extern __shared__ __align__(16) char gsm[];
    const uint32_t sbase = smem_u32(gsm);

    const int tid  = threadIdx.x;
    const int lane = tid & 31, warp = tid >> 5;
    const int wm = warp >> 1, wn = warp & 1;
    const int m0 = blockIdx.y * 128, n0 = blockIdx.x * 128;

    const int g = lane >> 3, lr = lane & 7;
    uint32_t offA[2][2], offB[4][2];
    #pragma unroll
    for (int t = 0; t < 2; t++) {
        int row = wm * 32 + t * 16 + (g & 1) * 8 + lr;
        #pragma unroll
        for (int ks = 0; ks < 2; ks++)
            offA[t][ks] = (uint32_t)(row * (RS * 2) + (ks * 16 + (g >> 1) * 8) * 2);
    }
    #pragma unroll
    for (int p = 0; p < 4; p++) {
        int row = wn * 64 + p * 16 + (g >> 1) * 8 + lr;
        #pragma unroll
        for (int ks = 0; ks < 2; ks++)
            offB[p][ks] = (uint32_t)(row * (RS * 2) + (ks * 16 + (g & 1) * 8) * 2);
    }

    const int rr = tid >> 2, cs = tid & 3;
    const uint32_t sof = (uint32_t)(rr * 80 + cs * 16);

    float acc[2][8][4];
    #pragma unroll
    for (int mt = 0; mt < 2; mt++)
        #pragma unroll
        for (int nt = 0; nt < 8; nt++)
            #pragma unroll
            for (int j = 0; j < 4; j++) acc[mt][nt][j] = 0.0f;

    const int nchunk = Kd >> 5;

#define G_ISSUE(buf, k0) do { \
    uint32_t sb_ = sbase + (buf) * GBUF; \
    _Pragma("unroll") \
    for (int i_ = 0; i_ < 2; i_++) { \
        int row_ = rr + i_ * 64; \
        uint32_t so_ = sof + (uint32_t)(i_ * 64 * 80); \
        size_t ga_ = (size_t)(m0 + row_) * Kd + (k0) + cs * 8; \
        size_t gb_ = (size_t)(n0 + row_) * Kd + (k0) + cs * 8; \
        cpa16(sb_ + so_,            Ah + ga_); \
        cpa16(sb_ + GARR + so_,     Al + ga_); \
        cpa16(sb_ + 2*GARR + so_,   Bh + gb_); \
        cpa16(sb_ + 3*GARR + so_,   Bl + gb_); \
    } \
    CP_COMMIT(); \
} while(0)

    G_ISSUE(0, 0);
    if (nchunk > 1) G_ISSUE(1, 32);

    for (int ck = 0; ck < nchunk; ck++) {
        if (ck + 1 < nchunk) { CP_WAIT1(); } else { CP_WAIT0(); }
        __syncthreads();
        uint32_t sb = sbase + (ck & 1) * GBUF;
        uint32_t aAh = sb, aAl = sb + GARR, aBh = sb + 2*GARR, aBl = sb + 3*GARR;
        #pragma unroll
        for (int ks = 0; ks < 2; ks++) {
            uint32_t ah[2][4], al[2][4];
            ldm4(ah[0], aAh + offA[0][ks]);
            ldm4(ah[1], aAh + offA[1][ks]);
            ldm4(al[0], aAl + offA[0][ks]);
            ldm4(al[1], aAl + offA[1][ks]);
            #pragma unroll
            for (int p = 0; p < 4; p++) {
                uint32_t bh[4], bl[4];
                ldm4(bh, aBh + offB[p][ks]);
                ldm4(bl, aBl + offB[p][ks]);
                #pragma unroll
                for (int j = 0; j < 2; j++) {
                    int nt = p * 2 + j;
                    uint32_t b0h = bh[j*2], b1h = bh[j*2+1];
                    uint32_t b0l = bl[j*2], b1l = bl[j*2+1];
                    #pragma unroll
                    for (int mt = 0; mt < 2; mt++) {
                        mma_bf16(acc[mt][nt], ah[mt], b0h, b1h);
                        mma_bf16(acc[mt][nt], ah[mt], b0l, b1l);
                        mma_bf16(acc[mt][nt], al[mt], b0h, b1h);
                    }
                }
            }
        }
        __syncthreads();
        if (ck + 2 < nchunk) G_ISSUE(ck & 1, (ck + 2) * 32);
    }

    // epilogue
    const int erow = m0 + wm * 32 + (lane >> 2);
    const int ecol = n0 + wn * 64 + (lane & 3) * 2;
    #pragma unroll
    for (int mt = 0; mt < 2; mt++) {
        #pragma unroll
        for (int nt = 0; nt < 8; nt++) {
            const int col = ecol + nt * 8;
            float2 bz = *(const float2*)&bias[col];
            float v0 = acc[mt][nt][0] + bz.x;
            float v1 = acc[mt][nt][1] + bz.y;
            float v2 = acc[mt][nt][2] + bz.x;
            float v3 = acc[mt][nt][3] + bz.y;
            const int r0 = erow + mt * 16, r1 = r0 + 8;
            if (EPI == 0) {
                v0 *= oscale; v1 *= oscale; v2 *= oscale; v3 *= oscale;
                uint32_t hw, lw;
                split2(v0, v1, hw, lw);
                *(uint32_t*)&Ch[(size_t)r0 * N + col] = hw;
                *(uint32_t*)&Cl[(size_t)r0 * N + col] = lw;
                split2(v2, v3, hw, lw);
                *(uint32_t*)&Ch[(size_t)r1 * N + col] = hw;
                *(uint32_t*)&Cl[(size_t)r1 * N + col] = lw;
            }
            if (EPI == 1) {
                v0 = gelu_tanh(v0); v1 = gelu_tanh(v1);
                v2 = gelu_tanh(v2); v3 = gelu_tanh(v3);
                uint32_t hw, lw;
                split2(v0, v1, hw, lw);
                *(uint32_t*)&Ch[(size_t)r0 * N + col] = hw;
                *(uint32_t*)&Cl[(size_t)r0 * N + col] = lw;
                split2(v2, v3, hw, lw);
                *(uint32_t*)&Ch[(size_t)r1 * N + col] = hw;
                *(uint32_t*)&Cl[(size_t)r1 * N + col] = lw;
            }
            if (EPI == 2) {
                float2 ra = *(const float2*)&res[(size_t)r0 * N + col];
                float2 rb = *(const float2*)&res[(size_t)r1 * N + col];
                float2 w0 = {v0 + ra.x, v1 + ra.y};
                float2 w1 = {v2 + rb.x, v3 + rb.y};
                *(float2*)&Cf[(size_t)r0 * N + col] = w0;
                *(float2*)&Cf[(size_t)r1 * N + col] = w1;
            }
        }
    }
#undef G_ISSUE
}

template <int EPI>
__global__ void __launch_bounds__(256, 2) mma_gemm2_kernel(
    const __nv_bfloat16* __restrict__ Ah, const __nv_bfloat16* __restrict__ Al,
    const __nv_bfloat16* __restrict__ Bh, const __nv_bfloat16* __restrict__ Bl,
    const float* __restrict__ bias, const float* __restrict__ res,
    float* __restrict__ Cf, __nv_bfloat16* __restrict__ Ch, __nv_bfloat16* __restrict__ Cl,
    int N, int Kd, float oscale)
{
    gemm2_core<EPI>(Ah, Al, Bh, Bl, bias, res, Cf, Ch, Cl, N, Kd, oscale);
}

__global__ void __launch_bounds__(256, 2) qkv2_kernel(
    const __nv_bfloat16* __restrict__ x1h, const __nv_bfloat16* __restrict__ x1l,
    const __nv_bfloat16* __restrict__ wqh, const __nv_bfloat16* __restrict__ wql, const float* __restrict__ bq,
    __nv_bfloat16* __restrict__ qh, __nv_bfloat16* __restrict__ ql,
    const __nv_bfloat16* __restrict__ wkh, const __nv_bfloat16* __restrict__ wkl, const float* __restrict__ bk,
    __nv_bfloat16* __restrict__ kh, __nv_bfloat16* __restrict__ kl,
    const __nv_bfloat16* __restrict__ wvh, const __nv_bfloat16* __restrict__ wvl, const float* __restrict__ bv,
    __nv_bfloat16* __restrict__ vh, __nv_bfloat16* __restrict__ vl)
{
    const float QSC = 0.125f * 1.4426950408889634f;   // fold 1/sqrt(K) * log2(e) into q
    const __nv_bfloat16 *Wh, *Wl; const float* bz; __nv_bfloat16 *Oh, *Ol; float sc;
    if (blockIdx.z == 0)      { Wh = wqh; Wl = wql; bz = bq; Oh = qh; Ol = ql; sc = QSC; }
    else if (blockIdx.z == 1) { Wh = wkh; Wl = wkl; bz = bk; Oh = kh; Ol = kl; sc = 1.0f; }
    else                      { Wh = wvh; Wl = wvl; bz = bv; Oh = vh; Ol = vl; sc = 1.0f; }
    gemm2_core<0>(x1h, x1l, Wh, Wl, bz, nullptr, nullptr, Oh, Ol, DD, DD, sc);
}

// ---------------- Flash attention: bf16 hi/lo inputs, cp.async double-buffered K/V ----------------
#define ASRB 144
#define QSZ  (128 * ASRB)      // 18432 B per Q array
#define KVSZ (64 * ASRB)       // 9216 B per K/V array
#define KVBUF (4 * KVSZ)       // 36864 B per stage
#define ATT_SMEM (2*QSZ + 2*KVBUF)   // 110592 B

__global__ void __launch_bounds__(256) attn_mma2_kernel(
    const __nv_bfloat16* __restrict__ Qh_, const __nv_bfloat16* __restrict__ Ql_,
    const __nv_bfloat16* __restrict__ Kh_, const __nv_bfloat16* __restrict__ Kl_,
    const __nv_bfloat16* __restrict__ Vh_, const __nv_bfloat16* __restrict__ Vl_,
    __nv_bfloat16* __restrict__ Oh, __nv_bfloat16* __restrict__ Ol)
{
    extern __shared__ __align__(16) char asmem[];
    const uint32_t base = smem_u32(asmem);
    const uint32_t aQh = base, aQl = base + QSZ;

    const int tid  = threadIdx.x;
    const int lane = tid & 31, warp = tid >> 5;
    const int b = blockIdx.y >> 3, h = blockIdx.y & 7;
    const int qt = blockIdx.x * 128;
    const size_t rowbase = (size_t)b * TT;

    // ---- Q tile: plain vector copy (already scaled + split by QKV epilogue) ----
    {
        const int rq = tid >> 3, cq = tid & 7;
        #pragma unroll
        for (int i = 0; i < 4; i++) {
            int row = rq + i * 32;
            size_t ga = (rowbase + qt + row) * DD + h * HK + cq * 8;
            uint4 th = *(const uint4*)(Qh_ + ga);
            uint4 tl = *(const uint4*)(Ql_ + ga);
            uint32_t so = (uint32_t)(row * ASRB + cq * 16);
            STS128Q(aQh + so, th);
            STS128Q(aQl + so, tl);
        }
    }

    const int g = lane >> 3, lr = lane & 7;
    const uint32_t qoff = (uint32_t)((warp * 16 + (g & 1) * 8 + lr) * ASRB + (g >> 1) * 16);
    const uint32_t koff = (uint32_t)(((g >> 1) * 8 + lr) * ASRB + (g & 1) * 16);
    const uint32_t voff = (uint32_t)(((g & 1) * 8 + lr) * ASRB + (g >> 1) * 16);

    const int rkv = tid >> 3, ckv = tid & 7;

#define KV_ISSUE(buf, kt) do { \
    uint32_t sb_ = base + 2*QSZ + (buf) * KVBUF; \
    _Pragma("unroll") \
    for (int i_ = 0; i_ < 2; i_++) { \
        int row_ = rkv + i_ * 32; \
        size_t ga_ = (rowbase + (size_t)(kt) * 64 + row_) * DD + h * HK + ckv * 8; \
        uint32_t so_ = (uint32_t)(row_ * ASRB + ckv * 16); \
        cpa16(sb_ + so_,            Kh_ + ga_); \
        cpa16(sb_ + KVSZ + so_,     Kl_ + ga_); \
        cpa16(sb_ + 2*KVSZ + so_,   Vh_ + ga_); \
        cpa16(sb_ + 3*KVSZ + so_,   Vl_ + ga_); \
    } \
    CP_COMMIT(); \
} while(0)

    float m0 = -1e30f, m1 = -1e30f, l0 = 0.0f, l1 = 0.0f;
    float oacc[8][4];
    #pragma unroll
    for (int nt = 0; nt < 8; nt++)
        #pragma unroll
        for (int j = 0; j < 4; j++) oacc[nt][j] = 0.0f;

    const int NTILE = TT / 64;
    KV_ISSUE(0, 0);
    KV_ISSUE(1, 1);

    for (int kt = 0; kt < NTILE; kt++) {
        if (kt + 1 < NTILE) { CP_WAIT1(); } else { CP_WAIT0(); }
        __syncthreads();
        uint32_t sb = base + 2*QSZ + (kt & 1) * KVBUF;
        uint32_t aKh = sb, aKl = sb + KVSZ, aVh = sb + 2*KVSZ, aVl = sb + 3*KVSZ;

        // ---- S = Q K^T ----
        float sacc[8][4];
        #pragma unroll
        for (int nt = 0; nt < 8; nt++)
            #pragma unroll
            for (int j = 0; j < 4; j++) sacc[nt][j] = 0.0f;

        #pragma unroll
        for (int ks = 0; ks < 4; ks++) {
            uint32_t qah[4], qal[4];
            ldm4(qah, aQh + qoff + ks * 32);
            ldm4(qal, aQl + qoff + ks * 32);
            #pragma unroll
            for (int p = 0; p < 4; p++) {
                uint32_t kh4[4], kl4[4];
                ldm4(kh4, aKh + koff + (uint32_t)(p * 16 * ASRB) + ks * 32);
                ldm4(kl4, aKl + koff + (uint32_t)(p * 16 * ASRB) + ks * 32);
                #pragma unroll
                for (int j = 0; j < 2; j++) {
                    int nt = p * 2 + j;
                    mma_bf16(sacc[nt], qah, kh4[j*2], kh4[j*2+1]);
                    mma_bf16(sacc[nt], qah, kl4[j*2], kl4[j*2+1]);
                    mma_bf16(sacc[nt], qal, kh4[j*2], kh4[j*2+1]);
                }
            }
        }

        // ---- online softmax (log2 domain) ----
        float mx0 = -1e30f, mx1 = -1e30f;
        #pragma unroll
        for (int nt = 0; nt < 8; nt++) {
            mx0 = fmaxf(mx0, fmaxf(sacc[nt][0], sacc[nt][1]));
            mx1 = fmaxf(mx1, fmaxf(sacc[nt][2], sacc[nt][3]));
        }
        mx0 = fmaxf(mx0, __shfl_xor_sync(0xffffffffu, mx0, 1));
        mx0 = fmaxf(mx0, __shfl_xor_sync(0xffffffffu, mx0, 2));
        mx1 = fmaxf(mx1, __shfl_xor_sync(0xffffffffu, mx1, 1));
        mx1 = fmaxf(mx1, __shfl_xor_sync(0xffffffffu, mx1, 2));
        float nm0 = fmaxf(m0, mx0), nm1 = fmaxf(m1, mx1);
        float al0 = ex2f(m0 - nm0), al1 = ex2f(m1 - nm1);
        m0 = nm0; m1 = nm1;
        #pragma unroll
        for (int nt = 0; nt < 8; nt++) {
            oacc[nt][0] *= al0; oacc[nt][1] *= al0;
            oacc[nt][2] *= al1; oacc[nt][3] *= al1;
        }
        float rs0 = 0.0f, rs1 = 0.0f;

        // ---- O += P V (P built in registers) ----
        #pragma unroll
        for (int kp = 0; kp < 4; kp++) {
            uint32_t pah[4], pal[4];
            #pragma unroll
            for (int j = 0; j < 2; j++) {
                int nt = 2 * kp + j;
                float p00 = ex2f(sacc[nt][0] - nm0);
                float p01 = ex2f(sacc[nt][1] - nm0);
                float p10 = ex2f(sacc[nt][2] - nm1);
                float p11 = ex2f(sacc[nt][3] - nm1);
                rs0 += p00 + p01; rs1 += p10 + p11;
                split2(p00, p01, pah[2 * j],     pal[2 * j]);
                split2(p10, p11, pah[2 * j + 1], pal[2 * j + 1]);
            }
            #pragma unroll
            for (int gv = 0; gv < 4; gv++) {
                uint32_t vh4[4], vl4[4];
                ldm4t(vh4, aVh + voff + (uint32_t)(kp * 16 * ASRB) + gv * 32);
                ldm4t(vl4, aVl + voff + (uint32_t)(kp * 16 * ASRB) + gv * 32);
                #pragma unroll
                for (int j = 0; j < 2; j++) {
                    int nt = gv * 2 + j;
                    mma_bf16(oacc[nt], pah, vh4[j*2], vh4[j*2+1]);
                    mma_bf16(oacc[nt], pah, vl4[j*2], vl4[j*2+1]);
                    mma_bf16(oacc[nt], pal, vh4[j*2], vh4[j*2+1]);
                }
            }
        }
        rs0 += __shfl_xor_sync(0xffffffffu, rs0, 1);
        rs0 += __shfl_xor_sync(0xffffffffu, rs0, 2);
        rs1 += __shfl_xor_sync(0xffffffffu, rs1, 1);
        rs1 += __shfl_xor_sync(0xffffffffu, rs1, 2);
        l0 = l0 * al0 + rs0;
        l1 = l1 * al1 + rs1;

        __syncthreads();
        if (kt + 2 < NTILE) KV_ISSUE(kt & 1, kt + 2);
    }

    // ---- write ctx as bf16 hi/lo ----
    const float inv0 = 1.0f / l0, inv1 = 1.0f / l1;
    const int qr0 = qt + warp * 16 + (lane >> 2);
    const int colb = h * HK + (lane & 3) * 2;
    #pragma unroll
    for (int nt = 0; nt < 8; nt++) {
        uint32_t hw, lw;
        split2(oacc[nt][0] * inv0, oacc[nt][1] * inv0, hw, lw);
        *(uint32_t*)&Oh[(rowbase + qr0) * DD + colb + nt * 8] = hw;
        *(uint32_t*)&Ol[(rowbase + qr0) * DD + colb + nt * 8] = lw;
        split2(oacc[nt][2] * inv1, oacc[nt][3] * inv1, hw, lw);
        *(uint32_t*)&Oh[(rowbase + qr0 + 8) * DD + colb + nt * 8] = hw;
        *(uint32_t*)&Ol[(rowbase + qr0 + 8) * DD + colb + nt * 8] = lw;
    }
#undef KV_ISSUE
}

// ---------------- launch ----------------
extern "C" void kernel_launch(void* const* d_in, const int* in_sizes, int n_in,
                              void* d_out, int out_size) {
    const float* inputs     = (const float*)d_in[0];
    const float* ln1_scale  = (const float*)d_in[1];
    const float* ln1_offset = (const float*)d_in[2];
    const float* wq = (const float*)d_in[3];
    const float* bq = (const float*)d_in[4];
    const float* wk = (const float*)d_in[5];
    const float* bk = (const float*)d_in[6];
    const float* wv = (const float*)d_in[7];
    const float* bv = (const float*)d_in[8];
    const float* wo = (const float*)d_in[9];
    const float* bo = (const float*)d_in[10];
    const float* ln2_scale  = (const float*)d_in[11];
    const float* ln2_offset = (const float*)d_in[12];
    const float* w1 = (const float*)d_in[13];
    const float* b1 = (const float*)d_in[14];
    const float* w2 = (const float*)d_in[15];
    const float* b2 = (const float*)d_in[16];
    float* out = (float*)d_out;

    __nv_bfloat16 *x1h, *x1l, *qh, *ql, *kh, *kl, *vh, *vl, *ctxh, *ctxl, *yh, *yl, *hh, *hl;
    __nv_bfloat16 *wtqh, *wtql, *wtkh, *wtkl, *wtvh, *wtvl, *wtoh, *wtol, *wt1h, *wt1l, *wt2h, *wt2l;
    float* x;
    cudaGetSymbolAddress((void**)&x1h, g_x1h);   cudaGetSymbolAddress((void**)&x1l, g_x1l);
    cudaGetSymbolAddress((void**)&qh,  g_qh);    cudaGetSymbolAddress((void**)&ql,  g_ql);
    cudaGetSymbolAddress((void**)&kh,  g_kh);    cudaGetSymbolAddress((void**)&kl,  g_kl);
    cudaGetSymbolAddress((void**)&vh,  g_vh);    cudaGetSymbolAddress((void**)&vl,  g_vl);
    cudaGetSymbolAddress((void**)&ctxh, g_ctxh); cudaGetSymbolAddress((void**)&ctxl, g_ctxl);
    cudaGetSymbolAddress((void**)&yh,  g_yh);    cudaGetSymbolAddress((void**)&yl,  g_yl);
    cudaGetSymbolAddress((void**)&hh,  g_hh);    cudaGetSymbolAddress((void**)&hl,  g_hl);
    cudaGetSymbolAddress((void**)&x,   g_x);
    cudaGetSymbolAddress((void**)&wtqh, g_wtqh); cudaGetSymbolAddress((void**)&wtql, g_wtql);
    cudaGetSymbolAddress((void**)&wtkh, g_wtkh); cudaGetSymbolAddress((void**)&wtkl, g_wtkl);
    cudaGetSymbolAddress((void**)&wtvh, g_wtvh); cudaGetSymbolAddress((void**)&wtvl, g_wtvl);
    cudaGetSymbolAddress((void**)&wtoh, g_wtoh); cudaGetSymbolAddress((void**)&wtol, g_wtol);
    cudaGetSymbolAddress((void**)&wt1h, g_wt1h); cudaGetSymbolAddress((void**)&wt1l, g_wt1l);
    cudaGetSymbolAddress((void**)&wt2h, g_wt2h); cudaGetSymbolAddress((void**)&wt2l, g_wt2l);

    cudaFuncSetAttribute(attn_mma2_kernel, cudaFuncAttributeMaxDynamicSharedMemorySize, ATT_SMEM);
    cudaFuncSetAttribute(mma_gemm2_kernel<1>, cudaFuncAttributeMaxDynamicSharedMemorySize, GEMM_SMEM);
    cudaFuncSetAttribute(mma_gemm2_kernel<2>, cudaFuncAttributeMaxDynamicSharedMemorySize, GEMM_SMEM);
    cudaFuncSetAttribute(qkv2_kernel,         cudaFuncAttributeMaxDynamicSharedMemorySize, GEMM_SMEM);

    // 0. weight transpose+split ([K,N] fp32 -> [N,K] bf16 hi/lo)
    tsplit_kernel<<<dim3(DD/32, DD/32), 256>>>(wq, wtqh, wtql, DD, DD);
    tsplit_kernel<<<dim3(DD/32, DD/32), 256>>>(wk, wtkh, wtkl, DD, DD);
    tsplit_kernel<<<dim3(DD/32, DD/32), 256>>>(wv, wtvh, wtvl, DD, DD);
    tsplit_kernel<<<dim3(DD/32, DD/32), 256>>>(wo, wtoh, wtol, DD, DD);
    tsplit_kernel<<<dim3(FF/32, DD/32), 256>>>(w1, wt1h, wt1l, DD, FF);
    tsplit_kernel<<<dim3(DD/32, FF/32), 256>>>(w2, wt2h, wt2l, FF, DD);

    // 1. LN1 -> bf16 hi/lo
    ln_kernel<<<MM, 128>>>(inputs, ln1_scale, ln1_offset, x1h, x1l);

    // 2. fused QKV projections (q pre-scaled by 0.125*log2e)
    qkv2_kernel<<<dim3(DD/128, MM/128, 3), 256, GEMM_SMEM>>>(
        x1h, x1l, wtqh, wtql, bq, qh, ql, wtkh, wtkl, bk, kh, kl, wtvh, wtvl, bv, vh, vl);

    // 3. flash attention -> ctx bf16 hi/lo
    attn_mma2_kernel<<<dim3(TT/128, BB*HH), 256, ATT_SMEM>>>(
        qh, ql, kh, kl, vh, vl, ctxh, ctxl);

    // 4. output projection + residual -> x fp32
    mma_gemm2_kernel<2><<<dim3(DD/128, MM/128), 256, GEMM_SMEM>>>(
        ctxh, ctxl, wtoh, wtol, bo, inputs, x, nullptr, nullptr, DD, DD, 1.0f);

    // 5. LN2 -> bf16 hi/lo
    ln_kernel<<<MM, 128>>>(x, ln2_scale, ln2_offset, yh, yl);

    // 6. FFN up + GELU -> h bf16 hi/lo
    mma_gemm2_kernel<1><<<dim3(FF/128, MM/128), 256, GEMM_SMEM>>>(
        yh, yl, wt1h, wt1l, b1, nullptr, nullptr, hh, hl, FF, DD, 1.0f);

    // 7. FFN down + residual -> out fp32
    mma_gemm2_kernel<2><<<dim3(DD/128, MM/128), 256, GEMM_SMEM>>>(
        hh, hl, wt2h, wt2l, b2, x, out, nullptr, nullptr, DD, FF, 1.0f);
}